// round 1
// baseline (speedup 1.0000x reference)
#include <cuda_runtime.h>
#include <math.h>

#define D_MODEL 1024
#define S_LEN   2048
#define BATCH   2
#define NHEADS  16
#define HDIM    64
#define M_TOT   (BATCH * S_LEN)   // 4096

// Scratch (no cudaMalloc allowed)
__device__ float g_Q[(size_t)M_TOT * D_MODEL];   // [B,S,H*hd] layout
__device__ float g_K[(size_t)M_TOT * HDIM];      // [B,S,hd]
__device__ float g_V[(size_t)M_TOT * HDIM];
__device__ float g_att[(size_t)M_TOT * D_MODEL]; // [B,S,H*hd]

// ---------------------------------------------------------------------------
// Tiled SGEMM + bias: C[M,N] = A[M,K] @ W[K,N] + bias[N]
// BM=BN=64, BK=16, 256 threads, 4x4 per thread.
// ---------------------------------------------------------------------------
__global__ __launch_bounds__(256) void sgemm_bias(
    const float* __restrict__ A, const float* __restrict__ W,
    const float* __restrict__ bias, float* __restrict__ C,
    int M, int N, int K)
{
    __shared__ float As[16][64];   // [k][m]
    __shared__ float Ws[16][64];   // [k][n]

    const int tid = threadIdx.x;
    const int tx  = tid & 15;      // 0..15 (n)
    const int ty  = tid >> 4;      // 0..15 (m)
    const int row0 = blockIdx.y * 64;
    const int col0 = blockIdx.x * 64;

    float acc[4][4] = {};

    for (int k0 = 0; k0 < K; k0 += 16) {
        // Load A tile: each thread one float4 along K
        {
            int m  = tid >> 2;            // 0..63
            int kq = (tid & 3) << 2;      // 0,4,8,12
            float4 v = *(const float4*)(A + (size_t)(row0 + m) * K + k0 + kq);
            As[kq + 0][m] = v.x;
            As[kq + 1][m] = v.y;
            As[kq + 2][m] = v.z;
            As[kq + 3][m] = v.w;
        }
        // Load W tile: each thread one float4 along N
        {
            int k  = tid >> 4;            // 0..15
            int n4 = (tid & 15) << 2;     // 0..60
            *(float4*)&Ws[k][n4] =
                *(const float4*)(W + (size_t)(k0 + k) * N + col0 + n4);
        }
        __syncthreads();

        #pragma unroll
        for (int k = 0; k < 16; k++) {
            float4 a4 = *(const float4*)&As[k][ty << 2];
            float4 w4 = *(const float4*)&Ws[k][tx << 2];
            float a[4] = {a4.x, a4.y, a4.z, a4.w};
            float w[4] = {w4.x, w4.y, w4.z, w4.w};
            #pragma unroll
            for (int i = 0; i < 4; i++)
                #pragma unroll
                for (int j = 0; j < 4; j++)
                    acc[i][j] += a[i] * w[j];
        }
        __syncthreads();
    }

    #pragma unroll
    for (int i = 0; i < 4; i++) {
        int r = row0 + (ty << 2) + i;
        #pragma unroll
        for (int j = 0; j < 4; j++) {
            int c = col0 + (tx << 2) + j;
            C[(size_t)r * N + c] = acc[i][j] + bias[c];
        }
    }
}

// ---------------------------------------------------------------------------
// Flash-style MQA attention.
// grid: (S/128, B*H), block: 128 threads. One thread = one query row.
// K/V are shared across heads (MQA), staged in SMEM in 64-key tiles.
// Q layout: [B,S,H*hd]; output att layout: [B,S,H*hd] (== [B,S,D]).
// ---------------------------------------------------------------------------
__global__ __launch_bounds__(128) void mqa_attn(
    const float* __restrict__ gQ, const float* __restrict__ gK,
    const float* __restrict__ gV, float* __restrict__ gatt)
{
    __shared__ float Kt[64 * 64];
    __shared__ float Vt[64 * 64];

    const int tid = threadIdx.x;
    const int qi  = blockIdx.x * 128 + tid;
    const int b   = blockIdx.y >> 4;
    const int h   = blockIdx.y & 15;

    float q[64], acc[64];
    {
        const float4* qp = (const float4*)(gQ + ((size_t)(b * S_LEN + qi)) * D_MODEL + h * HDIM);
        #pragma unroll
        for (int i = 0; i < 16; i++) {
            float4 v = qp[i];
            q[4*i+0] = v.x; q[4*i+1] = v.y; q[4*i+2] = v.z; q[4*i+3] = v.w;
        }
    }
    #pragma unroll
    for (int d = 0; d < 64; d++) acc[d] = 0.f;

    float mx = -1e30f, l = 0.f;

    const float4* kbase = (const float4*)(gK + (size_t)b * S_LEN * HDIM);
    const float4* vbase = (const float4*)(gV + (size_t)b * S_LEN * HDIM);

    for (int kt = 0; kt < S_LEN; kt += 64) {
        __syncthreads();   // protect previous tile reads
        #pragma unroll
        for (int i = 0; i < 8; i++) {
            int idx = i * 128 + tid;                 // 1024 float4 per tile
            ((float4*)Kt)[idx] = kbase[kt * 16 + idx];
            ((float4*)Vt)[idx] = vbase[kt * 16 + idx];
        }
        __syncthreads();

        #pragma unroll 2
        for (int j = 0; j < 64; j++) {
            const float4* kr = (const float4*)(Kt + j * 64);
            float s = 0.f;
            #pragma unroll
            for (int d = 0; d < 16; d++) {
                float4 kv = kr[d];
                s += q[4*d+0]*kv.x + q[4*d+1]*kv.y + q[4*d+2]*kv.z + q[4*d+3]*kv.w;
            }
            s *= 0.125f;   // 1/sqrt(64)

            if (s > mx) {  // lazy rescale — rare after warmup
                float f = __expf(mx - s);
                l *= f;
                #pragma unroll
                for (int d = 0; d < 64; d++) acc[d] *= f;
                mx = s;
            }
            float p = __expf(s - mx);
            l += p;
            const float4* vr = (const float4*)(Vt + j * 64);
            #pragma unroll
            for (int d = 0; d < 16; d++) {
                float4 vv = vr[d];
                acc[4*d+0] += p * vv.x;
                acc[4*d+1] += p * vv.y;
                acc[4*d+2] += p * vv.z;
                acc[4*d+3] += p * vv.w;
            }
        }
    }

    const float inv = 1.f / l;
    float4* op = (float4*)(gatt + ((size_t)(b * S_LEN + qi)) * D_MODEL + h * HDIM);
    #pragma unroll
    for (int i = 0; i < 16; i++) {
        float4 v;
        v.x = acc[4*i+0] * inv; v.y = acc[4*i+1] * inv;
        v.z = acc[4*i+2] * inv; v.w = acc[4*i+3] * inv;
        op[i] = v;
    }
}

// ---------------------------------------------------------------------------
extern "C" void kernel_launch(void* const* d_in, const int* in_sizes, int n_in,
                              void* d_out, int out_size)
{
    const float* x  = (const float*)d_in[0];
    const float* Wq = (const float*)d_in[1];
    const float* bq = (const float*)d_in[2];
    const float* Wk = (const float*)d_in[3];
    const float* bk = (const float*)d_in[4];
    const float* Wv = (const float*)d_in[5];
    const float* bv = (const float*)d_in[6];
    const float* Wo = (const float*)d_in[7];
    const float* bo = (const float*)d_in[8];
    float* out = (float*)d_out;

    float *Q, *Kp, *Vp, *att;
    cudaGetSymbolAddress((void**)&Q,   g_Q);
    cudaGetSymbolAddress((void**)&Kp,  g_K);
    cudaGetSymbolAddress((void**)&Vp,  g_V);
    cudaGetSymbolAddress((void**)&att, g_att);

    // Projections
    sgemm_bias<<<dim3(D_MODEL / 64, M_TOT / 64), 256>>>(x, Wq, bq, Q,  M_TOT, D_MODEL, D_MODEL);
    sgemm_bias<<<dim3(HDIM / 64,    M_TOT / 64), 256>>>(x, Wk, bk, Kp, M_TOT, HDIM,    D_MODEL);
    sgemm_bias<<<dim3(HDIM / 64,    M_TOT / 64), 256>>>(x, Wv, bv, Vp, M_TOT, HDIM,    D_MODEL);

    // Attention
    mqa_attn<<<dim3(S_LEN / 128, BATCH * NHEADS), 128>>>(Q, Kp, Vp, att);

    // Output projection
    sgemm_bias<<<dim3(D_MODEL / 64, M_TOT / 64), 256>>>(att, Wo, bo, out, M_TOT, D_MODEL, D_MODEL);
}

// round 2
// speedup vs baseline: 3.0572x; 3.0572x over previous
#include <cuda_runtime.h>
#include <math.h>
#include <stdint.h>

#define D_MODEL 1024
#define S_LEN   2048
#define BATCH   2
#define NHEADS  16
#define HDIM    64
#define M_TOT   (BATCH * S_LEN)   // 4096

// Scratch (no cudaMalloc allowed)
__device__ float g_Q[(size_t)M_TOT * D_MODEL];   // [B,S,H*hd]
__device__ float g_K[(size_t)M_TOT * HDIM];      // [B,S,hd]
__device__ float g_V[(size_t)M_TOT * HDIM];
__device__ float g_att[(size_t)M_TOT * D_MODEL]; // [B,S,H*hd]

// ---------------------------------------------------------------------------
// helpers
// ---------------------------------------------------------------------------
__device__ __forceinline__ float f2tf(float x) {
    uint32_t r;
    asm("cvt.rna.tf32.f32 %0, %1;" : "=r"(r) : "f"(x));
    return __uint_as_float(r);
}

// D += A(16x8,row) * B(8x8,col), tf32 inputs, fp32 accum
__device__ __forceinline__ void mma_tf32(float c[4],
    uint32_t a0, uint32_t a1, uint32_t a2, uint32_t a3,
    uint32_t b0, uint32_t b1)
{
    asm volatile(
        "mma.sync.aligned.m16n8k8.row.col.f32.tf32.tf32.f32 "
        "{%0,%1,%2,%3},{%4,%5,%6,%7},{%8,%9},{%0,%1,%2,%3};"
        : "+f"(c[0]), "+f"(c[1]), "+f"(c[2]), "+f"(c[3])
        : "r"(a0), "r"(a1), "r"(a2), "r"(a3), "r"(b0), "r"(b1));
}

// ---------------------------------------------------------------------------
// tf32 tensor-core GEMM + bias: C[M,N] = A[M,K] @ W[K,N] + bias
// BM=128, BN=64, BK=32; 256 threads = 8 warps (4m x 2n); warp tile 32x32.
// Smem strides 36 / 72 give conflict-free per-element fragment loads.
// ---------------------------------------------------------------------------
__global__ __launch_bounds__(256) void gemm_tf32(
    const float* __restrict__ A, const float* __restrict__ W,
    const float* __restrict__ bias, float* __restrict__ C,
    int M, int N, int K)
{
    __shared__ float As[128 * 36];   // [m][k] pad->36
    __shared__ float Ws[32 * 72];    // [k][n] pad->72

    const int tid  = threadIdx.x;
    const int warp = tid >> 5;
    const int lane = tid & 31;
    const int G = lane >> 2, T = lane & 3;
    const int wm = (warp & 3) * 32;
    const int wn = (warp >> 2) * 32;
    const int row0 = blockIdx.y * 128;
    const int col0 = blockIdx.x * 64;

    float acc[2][4][4] = {};

    for (int k0 = 0; k0 < K; k0 += 32) {
        #pragma unroll
        for (int p = 0; p < 4; p++) {
            int idx = p * 256 + tid;
            int m = idx >> 3, k4 = (idx & 7) << 2;
            float4 v = *(const float4*)(A + (size_t)(row0 + m) * K + k0 + k4);
            float4 o = {f2tf(v.x), f2tf(v.y), f2tf(v.z), f2tf(v.w)};
            *(float4*)&As[m * 36 + k4] = o;
        }
        #pragma unroll
        for (int p = 0; p < 2; p++) {
            int idx = p * 256 + tid;
            int k = idx >> 4, n4 = (idx & 15) << 2;
            float4 v = *(const float4*)(W + (size_t)(k0 + k) * N + col0 + n4);
            float4 o = {f2tf(v.x), f2tf(v.y), f2tf(v.z), f2tf(v.w)};
            *(float4*)&Ws[k * 72 + n4] = o;
        }
        __syncthreads();

        #pragma unroll
        for (int ks = 0; ks < 4; ks++) {
            int k8 = ks * 8;
            uint32_t af[2][4];
            #pragma unroll
            for (int mt = 0; mt < 2; mt++) {
                int r = wm + mt * 16 + G;
                af[mt][0] = __float_as_uint(As[r * 36 + k8 + T]);
                af[mt][1] = __float_as_uint(As[(r + 8) * 36 + k8 + T]);
                af[mt][2] = __float_as_uint(As[r * 36 + k8 + T + 4]);
                af[mt][3] = __float_as_uint(As[(r + 8) * 36 + k8 + T + 4]);
            }
            #pragma unroll
            for (int nt = 0; nt < 4; nt++) {
                int n = wn + nt * 8 + G;
                uint32_t b0 = __float_as_uint(Ws[(k8 + T) * 72 + n]);
                uint32_t b1 = __float_as_uint(Ws[(k8 + T + 4) * 72 + n]);
                mma_tf32(acc[0][nt], af[0][0], af[0][1], af[0][2], af[0][3], b0, b1);
                mma_tf32(acc[1][nt], af[1][0], af[1][1], af[1][2], af[1][3], b0, b1);
            }
        }
        __syncthreads();
    }

    #pragma unroll
    for (int mt = 0; mt < 2; mt++) {
        int r = row0 + wm + mt * 16 + G;
        #pragma unroll
        for (int nt = 0; nt < 4; nt++) {
            int c = col0 + wn + nt * 8 + 2 * T;
            float2 bv = *(const float2*)(bias + c);
            float2 v0 = {acc[mt][nt][0] + bv.x, acc[mt][nt][1] + bv.y};
            float2 v1 = {acc[mt][nt][2] + bv.x, acc[mt][nt][3] + bv.y};
            *(float2*)(C + (size_t)r * N + c)       = v0;
            *(float2*)(C + (size_t)(r + 8) * N + c) = v1;
        }
    }
}

// ---------------------------------------------------------------------------
// Scalar fp32 GEMM + bias (kept for the small, accuracy-critical K/V proj)
// ---------------------------------------------------------------------------
__global__ __launch_bounds__(256) void sgemm_bias(
    const float* __restrict__ A, const float* __restrict__ W,
    const float* __restrict__ bias, float* __restrict__ C,
    int M, int N, int K)
{
    __shared__ float As[16][64];
    __shared__ float Ws[16][64];

    const int tid = threadIdx.x;
    const int tx  = tid & 15;
    const int ty  = tid >> 4;
    const int row0 = blockIdx.y * 64;
    const int col0 = blockIdx.x * 64;

    float acc[4][4] = {};

    for (int k0 = 0; k0 < K; k0 += 16) {
        {
            int m  = tid >> 2;
            int kq = (tid & 3) << 2;
            float4 v = *(const float4*)(A + (size_t)(row0 + m) * K + k0 + kq);
            As[kq + 0][m] = v.x; As[kq + 1][m] = v.y;
            As[kq + 2][m] = v.z; As[kq + 3][m] = v.w;
        }
        {
            int k  = tid >> 4;
            int n4 = (tid & 15) << 2;
            *(float4*)&Ws[k][n4] = *(const float4*)(W + (size_t)(k0 + k) * N + col0 + n4);
        }
        __syncthreads();
        #pragma unroll
        for (int k = 0; k < 16; k++) {
            float4 a4 = *(const float4*)&As[k][ty << 2];
            float4 w4 = *(const float4*)&Ws[k][tx << 2];
            float a[4] = {a4.x, a4.y, a4.z, a4.w};
            float w[4] = {w4.x, w4.y, w4.z, w4.w};
            #pragma unroll
            for (int i = 0; i < 4; i++)
                #pragma unroll
                for (int j = 0; j < 4; j++)
                    acc[i][j] += a[i] * w[j];
        }
        __syncthreads();
    }

    #pragma unroll
    for (int i = 0; i < 4; i++) {
        int r = row0 + (ty << 2) + i;
        #pragma unroll
        for (int j = 0; j < 4; j++) {
            int c = col0 + (tx << 2) + j;
            C[(size_t)r * N + c] = acc[i][j] + bias[c];
        }
    }
}

// ---------------------------------------------------------------------------
// Tensor-core FlashAttention (MQA): grid (S/64, B*H), 128 threads (4 warps).
// 64 queries/block; 32-key tiles; QK^T and P*V via tf32 mma.
// Warp w owns query rows [w*16, w*16+16). P round-trips through smem,
// aliasing the dead K tile.
// ---------------------------------------------------------------------------
__global__ __launch_bounds__(128) void mqa_attn_tc(
    const float* __restrict__ gQ, const float* __restrict__ gK,
    const float* __restrict__ gV, float* __restrict__ gatt)
{
    __shared__ float Qs[64 * 72];   // [q][hd] tf32
    __shared__ float KP[32 * 72];   // K tile [key][hd]; aliased as P [64][36]
    __shared__ float Vs[32 * 72];   // [key][hd]

    const int tid  = threadIdx.x;
    const int warp = tid >> 5;
    const int lane = tid & 31;
    const int G = lane >> 2, T = lane & 3;
    const int q0 = blockIdx.x * 64;
    const int b  = blockIdx.y >> 4;
    const int h  = blockIdx.y & 15;
    const int qb = warp * 16;

    // Load Q tile once (tf32)
    const float* qsrc = gQ + ((size_t)(b * S_LEN + q0)) * D_MODEL + h * HDIM;
    #pragma unroll
    for (int p = 0; p < 8; p++) {
        int idx = p * 128 + tid;
        int r = idx >> 4, c4 = (idx & 15) << 2;
        float4 v = *(const float4*)(qsrc + (size_t)r * D_MODEL + c4);
        float4 o = {f2tf(v.x), f2tf(v.y), f2tf(v.z), f2tf(v.w)};
        *(float4*)&Qs[r * 72 + c4] = o;
    }

    float o_acc[8][4] = {};
    float m0 = -INFINITY, m1 = -INFINITY, l0 = 0.f, l1 = 0.f;

    const float* kbase = gK + (size_t)b * S_LEN * HDIM;
    const float* vbase = gV + (size_t)b * S_LEN * HDIM;

    for (int kt = 0; kt < S_LEN; kt += 32) {
        __syncthreads();   // previous tile fully consumed
        #pragma unroll
        for (int p = 0; p < 4; p++) {
            int idx = p * 128 + tid;
            int r = idx >> 4, c4 = (idx & 15) << 2;
            float4 kv = *(const float4*)(kbase + (size_t)(kt + r) * HDIM + c4);
            float4 vv = *(const float4*)(vbase + (size_t)(kt + r) * HDIM + c4);
            float4 ko = {f2tf(kv.x), f2tf(kv.y), f2tf(kv.z), f2tf(kv.w)};
            float4 vo = {f2tf(vv.x), f2tf(vv.y), f2tf(vv.z), f2tf(vv.w)};
            *(float4*)&KP[r * 72 + c4] = ko;
            *(float4*)&Vs[r * 72 + c4] = vo;
        }
        __syncthreads();

        // S = Q * K^T  (warp: 16 q-rows x 32 keys)
        float s[4][4] = {};
        #pragma unroll
        for (int ks = 0; ks < 8; ks++) {
            int k8 = ks * 8;
            uint32_t a0 = __float_as_uint(Qs[(qb + G) * 72 + k8 + T]);
            uint32_t a1 = __float_as_uint(Qs[(qb + G + 8) * 72 + k8 + T]);
            uint32_t a2 = __float_as_uint(Qs[(qb + G) * 72 + k8 + T + 4]);
            uint32_t a3 = __float_as_uint(Qs[(qb + G + 8) * 72 + k8 + T + 4]);
            #pragma unroll
            for (int nt = 0; nt < 4; nt++) {
                uint32_t b0 = __float_as_uint(KP[(nt * 8 + G) * 72 + k8 + T]);
                uint32_t b1 = __float_as_uint(KP[(nt * 8 + G) * 72 + k8 + T + 4]);
                mma_tf32(s[nt], a0, a1, a2, a3, b0, b1);
            }
        }

        // Online softmax. Thread holds rows (qb+G, qb+G+8) x cols {8nt+2T, +1}.
        float mx0 = -INFINITY, mx1 = -INFINITY;
        #pragma unroll
        for (int nt = 0; nt < 4; nt++) {
            s[nt][0] *= 0.125f; s[nt][1] *= 0.125f;
            s[nt][2] *= 0.125f; s[nt][3] *= 0.125f;
            mx0 = fmaxf(mx0, fmaxf(s[nt][0], s[nt][1]));
            mx1 = fmaxf(mx1, fmaxf(s[nt][2], s[nt][3]));
        }
        mx0 = fmaxf(mx0, __shfl_xor_sync(0xffffffffu, mx0, 1));
        mx0 = fmaxf(mx0, __shfl_xor_sync(0xffffffffu, mx0, 2));
        mx1 = fmaxf(mx1, __shfl_xor_sync(0xffffffffu, mx1, 1));
        mx1 = fmaxf(mx1, __shfl_xor_sync(0xffffffffu, mx1, 2));

        float mn0 = fmaxf(m0, mx0), mn1 = fmaxf(m1, mx1);
        float f0 = __expf(m0 - mn0), f1 = __expf(m1 - mn1);
        float r0 = 0.f, r1 = 0.f;
        #pragma unroll
        for (int nt = 0; nt < 4; nt++) {
            s[nt][0] = __expf(s[nt][0] - mn0);
            s[nt][1] = __expf(s[nt][1] - mn0);
            s[nt][2] = __expf(s[nt][2] - mn1);
            s[nt][3] = __expf(s[nt][3] - mn1);
            r0 += s[nt][0] + s[nt][1];
            r1 += s[nt][2] + s[nt][3];
        }
        r0 += __shfl_xor_sync(0xffffffffu, r0, 1);
        r0 += __shfl_xor_sync(0xffffffffu, r0, 2);
        r1 += __shfl_xor_sync(0xffffffffu, r1, 1);
        r1 += __shfl_xor_sync(0xffffffffu, r1, 2);
        l0 = l0 * f0 + r0;
        l1 = l1 * f1 + r1;
        m0 = mn0; m1 = mn1;
        #pragma unroll
        for (int ht = 0; ht < 8; ht++) {
            o_acc[ht][0] *= f0; o_acc[ht][1] *= f0;
            o_acc[ht][2] *= f1; o_acc[ht][3] *= f1;
        }

        __syncthreads();   // all warps done reading K tile -> reuse as P
        #pragma unroll
        for (int nt = 0; nt < 4; nt++) {
            KP[(qb + G) * 36 + nt * 8 + 2 * T]         = f2tf(s[nt][0]);
            KP[(qb + G) * 36 + nt * 8 + 2 * T + 1]     = f2tf(s[nt][1]);
            KP[(qb + G + 8) * 36 + nt * 8 + 2 * T]     = f2tf(s[nt][2]);
            KP[(qb + G + 8) * 36 + nt * 8 + 2 * T + 1] = f2tf(s[nt][3]);
        }
        __syncwarp();      // each warp reads only its own P rows

        // O += P * V
        #pragma unroll
        for (int ks = 0; ks < 4; ks++) {
            int k8 = ks * 8;
            uint32_t a0 = __float_as_uint(KP[(qb + G) * 36 + k8 + T]);
            uint32_t a1 = __float_as_uint(KP[(qb + G + 8) * 36 + k8 + T]);
            uint32_t a2 = __float_as_uint(KP[(qb + G) * 36 + k8 + T + 4]);
            uint32_t a3 = __float_as_uint(KP[(qb + G + 8) * 36 + k8 + T + 4]);
            #pragma unroll
            for (int ht = 0; ht < 8; ht++) {
                uint32_t b0 = __float_as_uint(Vs[(k8 + T) * 72 + ht * 8 + G]);
                uint32_t b1 = __float_as_uint(Vs[(k8 + T + 4) * 72 + ht * 8 + G]);
                mma_tf32(o_acc[ht], a0, a1, a2, a3, b0, b1);
            }
        }
    }

    // Epilogue: normalize and store
    float i0 = 1.f / l0, i1 = 1.f / l1;
    float* od  = gatt + ((size_t)(b * S_LEN + q0 + qb + G)) * D_MODEL + h * HDIM;
    float* od8 = od + (size_t)8 * D_MODEL;
    #pragma unroll
    for (int ht = 0; ht < 8; ht++) {
        int c = ht * 8 + 2 * T;
        float2 v0 = {o_acc[ht][0] * i0, o_acc[ht][1] * i0};
        float2 v1 = {o_acc[ht][2] * i1, o_acc[ht][3] * i1};
        *(float2*)(od + c)  = v0;
        *(float2*)(od8 + c) = v1;
    }
}

// ---------------------------------------------------------------------------
extern "C" void kernel_launch(void* const* d_in, const int* in_sizes, int n_in,
                              void* d_out, int out_size)
{
    const float* x  = (const float*)d_in[0];
    const float* Wq = (const float*)d_in[1];
    const float* bq = (const float*)d_in[2];
    const float* Wk = (const float*)d_in[3];
    const float* bk = (const float*)d_in[4];
    const float* Wv = (const float*)d_in[5];
    const float* bv = (const float*)d_in[6];
    const float* Wo = (const float*)d_in[7];
    const float* bo = (const float*)d_in[8];
    float* out = (float*)d_out;

    float *Q, *Kp, *Vp, *att;
    cudaGetSymbolAddress((void**)&Q,   g_Q);
    cudaGetSymbolAddress((void**)&Kp,  g_K);
    cudaGetSymbolAddress((void**)&Vp,  g_V);
    cudaGetSymbolAddress((void**)&att, g_att);

    // Q projection: tensor-core tf32
    gemm_tf32<<<dim3(D_MODEL / 64, M_TOT / 128), 256>>>(x, Wq, bq, Q, M_TOT, D_MODEL, D_MODEL);
    // K/V projections: scalar fp32 (small; protects accuracy budget)
    sgemm_bias<<<dim3(HDIM / 64, M_TOT / 64), 256>>>(x, Wk, bk, Kp, M_TOT, HDIM, D_MODEL);
    sgemm_bias<<<dim3(HDIM / 64, M_TOT / 64), 256>>>(x, Wv, bv, Vp, M_TOT, HDIM, D_MODEL);

    // Attention: tensor-core flash MQA
    mqa_attn_tc<<<dim3(S_LEN / 64, BATCH * NHEADS), 128>>>(Q, Kp, Vp, att);

    // Output projection: tensor-core tf32
    gemm_tf32<<<dim3(D_MODEL / 64, M_TOT / 128), 256>>>(att, Wo, bo, out, M_TOT, D_MODEL, D_MODEL);
}

// round 3
// speedup vs baseline: 4.7274x; 1.5463x over previous
#include <cuda_runtime.h>
#include <cuda_fp16.h>
#include <math.h>
#include <stdint.h>

#define D_MODEL 1024
#define S_LEN   2048
#define BATCH   2
#define NHEADS  16
#define HDIM    64
#define M_TOT   (BATCH * S_LEN)   // 4096

// Scratch (no cudaMalloc allowed)
__device__ float g_Q[(size_t)M_TOT * D_MODEL];   // [B,S,H*hd]
__device__ float g_K[(size_t)M_TOT * HDIM];      // [B,S,hd]
__device__ float g_V[(size_t)M_TOT * HDIM];
__device__ float g_att[(size_t)M_TOT * D_MODEL]; // [B,S,H*hd]

// ---------------------------------------------------------------------------
// helpers
// ---------------------------------------------------------------------------
__device__ __forceinline__ uint32_t s2u(const void* p) {
    return (uint32_t)__cvta_generic_to_shared(p);
}

__device__ __forceinline__ void ldsm4(uint32_t& r0, uint32_t& r1, uint32_t& r2, uint32_t& r3,
                                      const __half* p) {
    uint32_t a = s2u(p);
    asm volatile("ldmatrix.sync.aligned.m8n8.x4.shared.b16 {%0,%1,%2,%3},[%4];"
                 : "=r"(r0), "=r"(r1), "=r"(r2), "=r"(r3) : "r"(a));
}
__device__ __forceinline__ void ldsm4t(uint32_t& r0, uint32_t& r1, uint32_t& r2, uint32_t& r3,
                                       const __half* p) {
    uint32_t a = s2u(p);
    asm volatile("ldmatrix.sync.aligned.m8n8.x4.trans.shared.b16 {%0,%1,%2,%3},[%4];"
                 : "=r"(r0), "=r"(r1), "=r"(r2), "=r"(r3) : "r"(a));
}

// C(16x8,f32) += A(16x16,f16) * B(16x8,f16)
__device__ __forceinline__ void mma16816(float c[4],
    uint32_t a0, uint32_t a1, uint32_t a2, uint32_t a3, uint32_t b0, uint32_t b1) {
    asm volatile(
        "mma.sync.aligned.m16n8k16.row.col.f32.f16.f16.f32 "
        "{%0,%1,%2,%3},{%4,%5,%6,%7},{%8,%9},{%0,%1,%2,%3};"
        : "+f"(c[0]), "+f"(c[1]), "+f"(c[2]), "+f"(c[3])
        : "r"(a0), "r"(a1), "r"(a2), "r"(a3), "r"(b0), "r"(b1));
}

__device__ __forceinline__ uint32_t packh2(float lo, float hi) {
    __half2 h = __floats2half2_rn(lo, hi);
    return *(uint32_t*)&h;
}

// ---------------------------------------------------------------------------
// fp16 tensor-core GEMM + bias: C[M,N] = A[M,K] @ W[K,N] + bias  (f32 accum)
// BM=128, BN=64, BK=32; 256 threads = 8 warps (4m x 2n); warp tile 32x32.
// ---------------------------------------------------------------------------
__global__ __launch_bounds__(256) void gemm_f16(
    const float* __restrict__ A, const float* __restrict__ W,
    const float* __restrict__ bias, float* __restrict__ C,
    int M, int N, int K)
{
    __shared__ __half As[128 * 40];   // [m][k] stride 40 (conflict-free ldsm)
    __shared__ __half Ws[32 * 72];    // [k][n] stride 72

    const int tid  = threadIdx.x;
    const int warp = tid >> 5;
    const int lane = tid & 31;
    const int G = lane >> 2, T = lane & 3;
    const int wm = (warp & 3) * 32;
    const int wn = (warp >> 2) * 32;
    const int row0 = blockIdx.y * 128;
    const int col0 = blockIdx.x * 64;

    float acc[2][4][4] = {};

    for (int k0 = 0; k0 < K; k0 += 32) {
        #pragma unroll
        for (int p = 0; p < 4; p++) {
            int idx = p * 256 + tid;
            int m = idx >> 3, k4 = (idx & 7) << 2;
            float4 v = *(const float4*)(A + (size_t)(row0 + m) * K + k0 + k4);
            uint2 h = {packh2(v.x, v.y), packh2(v.z, v.w)};
            *(uint2*)&As[m * 40 + k4] = h;
        }
        #pragma unroll
        for (int p = 0; p < 2; p++) {
            int idx = p * 256 + tid;
            int k = idx >> 4, n4 = (idx & 15) << 2;
            float4 v = *(const float4*)(W + (size_t)(k0 + k) * N + col0 + n4);
            uint2 h = {packh2(v.x, v.y), packh2(v.z, v.w)};
            *(uint2*)&Ws[k * 72 + n4] = h;
        }
        __syncthreads();

        #pragma unroll
        for (int kc = 0; kc < 2; kc++) {
            uint32_t af[2][4];
            #pragma unroll
            for (int mt = 0; mt < 2; mt++)
                ldsm4(af[mt][0], af[mt][1], af[mt][2], af[mt][3],
                      &As[(wm + mt * 16 + (lane & 15)) * 40 + kc * 16 + (lane >> 4) * 8]);
            #pragma unroll
            for (int np = 0; np < 2; np++) {
                uint32_t b0, b1, b2, b3;
                ldsm4t(b0, b1, b2, b3,
                       &Ws[(kc * 16 + (lane & 15)) * 72 + wn + np * 16 + (lane >> 4) * 8]);
                #pragma unroll
                for (int mt = 0; mt < 2; mt++) {
                    mma16816(acc[mt][np * 2],     af[mt][0], af[mt][1], af[mt][2], af[mt][3], b0, b1);
                    mma16816(acc[mt][np * 2 + 1], af[mt][0], af[mt][1], af[mt][2], af[mt][3], b2, b3);
                }
            }
        }
        __syncthreads();
    }

    #pragma unroll
    for (int mt = 0; mt < 2; mt++) {
        int r = row0 + wm + mt * 16 + G;
        #pragma unroll
        for (int nt = 0; nt < 4; nt++) {
            int c = col0 + wn + nt * 8 + 2 * T;
            float2 bv = *(const float2*)(bias + c);
            float2 v0 = {acc[mt][nt][0] + bv.x, acc[mt][nt][1] + bv.y};
            float2 v1 = {acc[mt][nt][2] + bv.x, acc[mt][nt][3] + bv.y};
            *(float2*)(C + (size_t)r * N + c)       = v0;
            *(float2*)(C + (size_t)(r + 8) * N + c) = v1;
        }
    }
}

// ---------------------------------------------------------------------------
// Scalar fp32 GEMM + bias (small, accuracy-critical K/V projections)
// ---------------------------------------------------------------------------
__global__ __launch_bounds__(256) void sgemm_bias(
    const float* __restrict__ A, const float* __restrict__ W,
    const float* __restrict__ bias, float* __restrict__ C,
    int M, int N, int K)
{
    __shared__ float As[16][64];
    __shared__ float Ws[16][64];

    const int tid = threadIdx.x;
    const int tx  = tid & 15;
    const int ty  = tid >> 4;
    const int row0 = blockIdx.y * 64;
    const int col0 = blockIdx.x * 64;

    float acc[4][4] = {};

    for (int k0 = 0; k0 < K; k0 += 16) {
        {
            int m  = tid >> 2;
            int kq = (tid & 3) << 2;
            float4 v = *(const float4*)(A + (size_t)(row0 + m) * K + k0 + kq);
            As[kq + 0][m] = v.x; As[kq + 1][m] = v.y;
            As[kq + 2][m] = v.z; As[kq + 3][m] = v.w;
        }
        {
            int k  = tid >> 4;
            int n4 = (tid & 15) << 2;
            *(float4*)&Ws[k][n4] = *(const float4*)(W + (size_t)(k0 + k) * N + col0 + n4);
        }
        __syncthreads();
        #pragma unroll
        for (int k = 0; k < 16; k++) {
            float4 a4 = *(const float4*)&As[k][ty << 2];
            float4 w4 = *(const float4*)&Ws[k][tx << 2];
            float a[4] = {a4.x, a4.y, a4.z, a4.w};
            float w[4] = {w4.x, w4.y, w4.z, w4.w};
            #pragma unroll
            for (int i = 0; i < 4; i++)
                #pragma unroll
                for (int j = 0; j < 4; j++)
                    acc[i][j] += a[i] * w[j];
        }
        __syncthreads();
    }

    #pragma unroll
    for (int i = 0; i < 4; i++) {
        int r = row0 + (ty << 2) + i;
        #pragma unroll
        for (int j = 0; j < 4; j++) {
            int c = col0 + (tx << 2) + j;
            C[(size_t)r * N + c] = acc[i][j] + bias[c];
        }
    }
}

// ---------------------------------------------------------------------------
// fp16 tensor-core FlashAttention (MQA).
// grid (S/128, B*H), 256 threads (8 warps). 128 queries/block, 64-key tiles.
// Q fragments live in registers (loop-invariant). P never touches smem:
// fp16 m16n8k16 C-fragment layout == A-fragment layout.
// ---------------------------------------------------------------------------
__global__ __launch_bounds__(256) void mqa_attn_f16(
    const float* __restrict__ gQ, const float* __restrict__ gK,
    const float* __restrict__ gV, float* __restrict__ gatt)
{
    __shared__ __half Qs[128 * 72];
    __shared__ __half Ks[64 * 72];
    __shared__ __half Vs[64 * 72];

    const int tid  = threadIdx.x;
    const int warp = tid >> 5;
    const int lane = tid & 31;
    const int G = lane >> 2, T = lane & 3;
    const int q0 = blockIdx.x * 128;
    const int b  = blockIdx.y >> 4;
    const int h  = blockIdx.y & 15;
    const int qb = warp * 16;

    // Load Q tile (pre-scaled by 1/sqrt(hd) = 0.125, exact)
    {
        const float* qsrc = gQ + ((size_t)(b * S_LEN + q0)) * D_MODEL + h * HDIM;
        #pragma unroll
        for (int p = 0; p < 8; p++) {
            int idx = p * 256 + tid;
            int r = idx >> 4, c4 = (idx & 15) << 2;
            float4 v = *(const float4*)(qsrc + (size_t)r * D_MODEL + c4);
            uint2 hh = {packh2(v.x * 0.125f, v.y * 0.125f),
                        packh2(v.z * 0.125f, v.w * 0.125f)};
            *(uint2*)&Qs[r * 72 + c4] = hh;
        }
    }
    __syncthreads();

    // Hoist Q fragments into registers: 4 k-chunks of 16
    uint32_t qf[4][4];
    #pragma unroll
    for (int kc = 0; kc < 4; kc++)
        ldsm4(qf[kc][0], qf[kc][1], qf[kc][2], qf[kc][3],
              &Qs[(qb + (lane & 15)) * 72 + kc * 16 + (lane >> 4) * 8]);

    float o_acc[8][4] = {};
    float m0 = -INFINITY, m1 = -INFINITY, l0 = 0.f, l1 = 0.f;

    const float* kbase = gK + (size_t)b * S_LEN * HDIM;
    const float* vbase = gV + (size_t)b * S_LEN * HDIM;

    for (int kt = 0; kt < S_LEN; kt += 64) {
        __syncthreads();   // previous tile fully consumed
        #pragma unroll
        for (int p = 0; p < 4; p++) {
            int idx = p * 256 + tid;
            int r = idx >> 4, c4 = (idx & 15) << 2;
            float4 kv = *(const float4*)(kbase + (size_t)(kt + r) * HDIM + c4);
            float4 vv = *(const float4*)(vbase + (size_t)(kt + r) * HDIM + c4);
            uint2 kh = {packh2(kv.x, kv.y), packh2(kv.z, kv.w)};
            uint2 vh = {packh2(vv.x, vv.y), packh2(vv.z, vv.w)};
            *(uint2*)&Ks[r * 72 + c4] = kh;
            *(uint2*)&Vs[r * 72 + c4] = vh;
        }
        __syncthreads();

        // S = Q * K^T : 16 q-rows x 64 keys per warp
        float s[8][4];
        #pragma unroll
        for (int nt = 0; nt < 8; nt++) { s[nt][0]=0.f; s[nt][1]=0.f; s[nt][2]=0.f; s[nt][3]=0.f; }
        #pragma unroll
        for (int nt = 0; nt < 8; nt++) {
            uint32_t b0, b1, b2, b3, b4, b5, b6, b7;
            const __half* kp = &Ks[(nt * 8 + (lane & 7)) * 72 + ((lane >> 3) * 8)];
            ldsm4(b0, b1, b2, b3, kp);
            ldsm4(b4, b5, b6, b7, kp + 32);
            mma16816(s[nt], qf[0][0], qf[0][1], qf[0][2], qf[0][3], b0, b1);
            mma16816(s[nt], qf[1][0], qf[1][1], qf[1][2], qf[1][3], b2, b3);
            mma16816(s[nt], qf[2][0], qf[2][1], qf[2][2], qf[2][3], b4, b5);
            mma16816(s[nt], qf[3][0], qf[3][1], qf[3][2], qf[3][3], b6, b7);
        }

        // Online softmax (rows qb+G and qb+G+8)
        float mx0 = -INFINITY, mx1 = -INFINITY;
        #pragma unroll
        for (int nt = 0; nt < 8; nt++) {
            mx0 = fmaxf(mx0, fmaxf(s[nt][0], s[nt][1]));
            mx1 = fmaxf(mx1, fmaxf(s[nt][2], s[nt][3]));
        }
        mx0 = fmaxf(mx0, __shfl_xor_sync(0xffffffffu, mx0, 1));
        mx0 = fmaxf(mx0, __shfl_xor_sync(0xffffffffu, mx0, 2));
        mx1 = fmaxf(mx1, __shfl_xor_sync(0xffffffffu, mx1, 1));
        mx1 = fmaxf(mx1, __shfl_xor_sync(0xffffffffu, mx1, 2));

        float mn0 = fmaxf(m0, mx0), mn1 = fmaxf(m1, mx1);
        float f0 = __expf(m0 - mn0), f1 = __expf(m1 - mn1);
        float r0 = 0.f, r1 = 0.f;
        #pragma unroll
        for (int nt = 0; nt < 8; nt++) {
            s[nt][0] = __expf(s[nt][0] - mn0);
            s[nt][1] = __expf(s[nt][1] - mn0);
            s[nt][2] = __expf(s[nt][2] - mn1);
            s[nt][3] = __expf(s[nt][3] - mn1);
            r0 += s[nt][0] + s[nt][1];
            r1 += s[nt][2] + s[nt][3];
        }
        r0 += __shfl_xor_sync(0xffffffffu, r0, 1);
        r0 += __shfl_xor_sync(0xffffffffu, r0, 2);
        r1 += __shfl_xor_sync(0xffffffffu, r1, 1);
        r1 += __shfl_xor_sync(0xffffffffu, r1, 2);
        l0 = l0 * f0 + r0;
        l1 = l1 * f1 + r1;
        m0 = mn0; m1 = mn1;
        #pragma unroll
        for (int ht = 0; ht < 8; ht++) {
            o_acc[ht][0] *= f0; o_acc[ht][1] *= f0;
            o_acc[ht][2] *= f1; o_acc[ht][3] *= f1;
        }

        // O += P * V : P packs straight into A fragments (no smem!)
        #pragma unroll
        for (int ks = 0; ks < 4; ks++) {
            uint32_t a0 = packh2(s[2*ks][0],   s[2*ks][1]);
            uint32_t a1 = packh2(s[2*ks][2],   s[2*ks][3]);
            uint32_t a2 = packh2(s[2*ks+1][0], s[2*ks+1][1]);
            uint32_t a3 = packh2(s[2*ks+1][2], s[2*ks+1][3]);
            #pragma unroll
            for (int hp = 0; hp < 4; hp++) {
                uint32_t b0, b1, b2, b3;
                ldsm4t(b0, b1, b2, b3,
                       &Vs[(ks * 16 + (lane & 15)) * 72 + hp * 16 + (lane >> 4) * 8]);
                mma16816(o_acc[hp * 2],     a0, a1, a2, a3, b0, b1);
                mma16816(o_acc[hp * 2 + 1], a0, a1, a2, a3, b2, b3);
            }
        }
    }

    // Epilogue
    float i0 = 1.f / l0, i1 = 1.f / l1;
    float* od  = gatt + ((size_t)(b * S_LEN + q0 + qb + G)) * D_MODEL + h * HDIM;
    float* od8 = od + (size_t)8 * D_MODEL;
    #pragma unroll
    for (int ht = 0; ht < 8; ht++) {
        int c = ht * 8 + 2 * T;
        float2 v0 = {o_acc[ht][0] * i0, o_acc[ht][1] * i0};
        float2 v1 = {o_acc[ht][2] * i1, o_acc[ht][3] * i1};
        *(float2*)(od + c)  = v0;
        *(float2*)(od8 + c) = v1;
    }
}

// ---------------------------------------------------------------------------
extern "C" void kernel_launch(void* const* d_in, const int* in_sizes, int n_in,
                              void* d_out, int out_size)
{
    const float* x  = (const float*)d_in[0];
    const float* Wq = (const float*)d_in[1];
    const float* bq = (const float*)d_in[2];
    const float* Wk = (const float*)d_in[3];
    const float* bk = (const float*)d_in[4];
    const float* Wv = (const float*)d_in[5];
    const float* bv = (const float*)d_in[6];
    const float* Wo = (const float*)d_in[7];
    const float* bo = (const float*)d_in[8];
    float* out = (float*)d_out;

    float *Q, *Kp, *Vp, *att;
    cudaGetSymbolAddress((void**)&Q,   g_Q);
    cudaGetSymbolAddress((void**)&Kp,  g_K);
    cudaGetSymbolAddress((void**)&Vp,  g_V);
    cudaGetSymbolAddress((void**)&att, g_att);

    // Q projection: fp16 tensor-core
    gemm_f16<<<dim3(D_MODEL / 64, M_TOT / 128), 256>>>(x, Wq, bq, Q, M_TOT, D_MODEL, D_MODEL);
    // K/V projections: scalar fp32 (small; protects accuracy budget)
    sgemm_bias<<<dim3(HDIM / 64, M_TOT / 64), 256>>>(x, Wk, bk, Kp, M_TOT, HDIM, D_MODEL);
    sgemm_bias<<<dim3(HDIM / 64, M_TOT / 64), 256>>>(x, Wv, bv, Vp, M_TOT, HDIM, D_MODEL);

    // Attention: fp16 flash MQA
    mqa_attn_f16<<<dim3(S_LEN / 128, BATCH * NHEADS), 256>>>(Q, Kp, Vp, att);

    // Output projection: fp16 tensor-core
    gemm_f16<<<dim3(D_MODEL / 64, M_TOT / 128), 256>>>(att, Wo, bo, out, M_TOT, D_MODEL, D_MODEL);
}

// round 4
// speedup vs baseline: 6.1604x; 1.3031x over previous
#include <cuda_runtime.h>
#include <cuda_fp16.h>
#include <math.h>
#include <stdint.h>

#define D_MODEL 1024
#define S_LEN   2048
#define BATCH   2
#define NHEADS  16
#define HDIM    64
#define M_TOT   (BATCH * S_LEN)   // 4096

// Scratch (no cudaMalloc allowed)
__device__ __half g_xh [(size_t)M_TOT * D_MODEL];
__device__ __half g_Wqh[(size_t)D_MODEL * D_MODEL];
__device__ __half g_Woh[(size_t)D_MODEL * D_MODEL];
__device__ __half g_Qh [(size_t)M_TOT * D_MODEL];
__device__ __half g_Kh [(size_t)M_TOT * HDIM];
__device__ __half g_Vh [(size_t)M_TOT * HDIM];
__device__ __half g_ah [(size_t)M_TOT * D_MODEL];

// ---------------------------------------------------------------------------
// helpers
// ---------------------------------------------------------------------------
__device__ __forceinline__ uint32_t s2u(const void* p) {
    return (uint32_t)__cvta_generic_to_shared(p);
}
__device__ __forceinline__ void cp16(void* s, const void* g) {
    asm volatile("cp.async.cg.shared.global [%0],[%1],16;\n"
                 :: "r"(s2u(s)), "l"(g));
}
__device__ __forceinline__ void cp_commit() {
    asm volatile("cp.async.commit_group;\n");
}
template<int N> __device__ __forceinline__ void cp_wait() {
    asm volatile("cp.async.wait_group %0;\n" :: "n"(N));
}
__device__ __forceinline__ void ldsm4(uint32_t& r0, uint32_t& r1, uint32_t& r2, uint32_t& r3,
                                      const __half* p) {
    asm volatile("ldmatrix.sync.aligned.m8n8.x4.shared.b16 {%0,%1,%2,%3},[%4];"
                 : "=r"(r0), "=r"(r1), "=r"(r2), "=r"(r3) : "r"(s2u(p)));
}
__device__ __forceinline__ void ldsm4t(uint32_t& r0, uint32_t& r1, uint32_t& r2, uint32_t& r3,
                                       const __half* p) {
    asm volatile("ldmatrix.sync.aligned.m8n8.x4.trans.shared.b16 {%0,%1,%2,%3},[%4];"
                 : "=r"(r0), "=r"(r1), "=r"(r2), "=r"(r3) : "r"(s2u(p)));
}
__device__ __forceinline__ void mma16816(float c[4],
    uint32_t a0, uint32_t a1, uint32_t a2, uint32_t a3, uint32_t b0, uint32_t b1) {
    asm volatile(
        "mma.sync.aligned.m16n8k16.row.col.f32.f16.f16.f32 "
        "{%0,%1,%2,%3},{%4,%5,%6,%7},{%8,%9},{%0,%1,%2,%3};"
        : "+f"(c[0]), "+f"(c[1]), "+f"(c[2]), "+f"(c[3])
        : "r"(a0), "r"(a1), "r"(a2), "r"(a3), "r"(b0), "r"(b1));
}
__device__ __forceinline__ uint32_t packh2(float lo, float hi) {
    __half2 h = __floats2half2_rn(lo, hi);
    return *(uint32_t*)&h;
}
__device__ __forceinline__ float ex2(float x) {
    float y; asm("ex2.approx.f32 %0,%1;" : "=f"(y) : "f"(x)); return y;
}

// ---------------------------------------------------------------------------
// fp32 -> fp16 bulk convert (8 elements/thread)
// ---------------------------------------------------------------------------
__global__ __launch_bounds__(256) void f2h(const float* __restrict__ src,
                                           __half* __restrict__ dst, int n)
{
    int i = (blockIdx.x * 256 + threadIdx.x) * 8;
    if (i < n) {
        float4 a = *(const float4*)(src + i);
        float4 b = *(const float4*)(src + i + 4);
        uint4 o = {packh2(a.x, a.y), packh2(a.z, a.w),
                   packh2(b.x, b.y), packh2(b.z, b.w)};
        *(uint4*)(dst + i) = o;
    }
}

// ---------------------------------------------------------------------------
// half-input tensor GEMM + bias: C = A_h[M,K] @ W_h[K,N] + bias (f32 accum)
// BM=128, BN=64, BK=32; 256 thr = 8 warps (4m x 2n); cp.async double buffer.
// ---------------------------------------------------------------------------
template<bool OUT_HALF>
__global__ __launch_bounds__(256) void gemm_h(
    const __half* __restrict__ A, const __half* __restrict__ W,
    const float* __restrict__ bias, void* __restrict__ Cv,
    int M, int N, int K)
{
    __shared__ __half As[2][128 * 40];
    __shared__ __half Ws[2][32 * 72];

    const int tid  = threadIdx.x;
    const int warp = tid >> 5;
    const int lane = tid & 31;
    const int G = lane >> 2, T = lane & 3;
    const int wm = (warp & 3) * 32;
    const int wn = (warp >> 2) * 32;
    const int row0 = blockIdx.y * 128;
    const int col0 = blockIdx.x * 64;

    const int am = tid >> 2;             // A chunk row for p=0 (0..63)
    const int ac = (tid & 3) * 8;        // A chunk col offset in halves
    const int wk = tid >> 3;             // W chunk row (0..31)
    const int wn8 = (tid & 7) * 8;       // W chunk col

    auto load_stage = [&](int st, int k0) {
        cp16(&As[st][am * 40 + ac],        A + (size_t)(row0 + am) * K + k0 + ac);
        cp16(&As[st][(am + 64) * 40 + ac], A + (size_t)(row0 + am + 64) * K + k0 + ac);
        cp16(&Ws[st][wk * 72 + wn8],       W + (size_t)(k0 + wk) * N + col0 + wn8);
    };

    float acc[2][4][4] = {};
    const int NK = K >> 5;

    load_stage(0, 0);
    cp_commit();

    for (int i = 0; i < NK; i++) {
        int st = i & 1;
        if (i + 1 < NK) load_stage(st ^ 1, (i + 1) << 5);
        cp_commit();
        cp_wait<1>();
        __syncthreads();

        #pragma unroll
        for (int kc = 0; kc < 2; kc++) {
            uint32_t af[2][4];
            #pragma unroll
            for (int mt = 0; mt < 2; mt++)
                ldsm4(af[mt][0], af[mt][1], af[mt][2], af[mt][3],
                      &As[st][(wm + mt * 16 + (lane & 15)) * 40 + kc * 16 + (lane >> 4) * 8]);
            #pragma unroll
            for (int np = 0; np < 2; np++) {
                uint32_t b0, b1, b2, b3;
                ldsm4t(b0, b1, b2, b3,
                       &Ws[st][(kc * 16 + (lane & 15)) * 72 + wn + np * 16 + (lane >> 4) * 8]);
                #pragma unroll
                for (int mt = 0; mt < 2; mt++) {
                    mma16816(acc[mt][np * 2],     af[mt][0], af[mt][1], af[mt][2], af[mt][3], b0, b1);
                    mma16816(acc[mt][np * 2 + 1], af[mt][0], af[mt][1], af[mt][2], af[mt][3], b2, b3);
                }
            }
        }
        __syncthreads();
    }

    #pragma unroll
    for (int mt = 0; mt < 2; mt++) {
        int r = row0 + wm + mt * 16 + G;
        #pragma unroll
        for (int nt = 0; nt < 4; nt++) {
            int c = col0 + wn + nt * 8 + 2 * T;
            float2 bv = *(const float2*)(bias + c);
            float v00 = acc[mt][nt][0] + bv.x, v01 = acc[mt][nt][1] + bv.y;
            float v10 = acc[mt][nt][2] + bv.x, v11 = acc[mt][nt][3] + bv.y;
            if (OUT_HALF) {
                __half* C = (__half*)Cv;
                *(uint32_t*)(C + (size_t)r * N + c)       = packh2(v00, v01);
                *(uint32_t*)(C + (size_t)(r + 8) * N + c) = packh2(v10, v11);
            } else {
                float* C = (float*)Cv;
                float2 a0 = {v00, v01}, a1 = {v10, v11};
                *(float2*)(C + (size_t)r * N + c)       = a0;
                *(float2*)(C + (size_t)(r + 8) * N + c) = a1;
            }
        }
    }
}

// ---------------------------------------------------------------------------
// Scalar fp32 GEMM + bias -> half output (accuracy-critical K/V projections)
// ---------------------------------------------------------------------------
__global__ __launch_bounds__(256) void sgemm_bias_h(
    const float* __restrict__ A, const float* __restrict__ W,
    const float* __restrict__ bias, __half* __restrict__ C,
    int M, int N, int K)
{
    __shared__ float As[16][64];
    __shared__ float Ws[16][64];

    const int tid = threadIdx.x;
    const int tx  = tid & 15;
    const int ty  = tid >> 4;
    const int row0 = blockIdx.y * 64;
    const int col0 = blockIdx.x * 64;

    float acc[4][4] = {};

    for (int k0 = 0; k0 < K; k0 += 16) {
        {
            int m  = tid >> 2;
            int kq = (tid & 3) << 2;
            float4 v = *(const float4*)(A + (size_t)(row0 + m) * K + k0 + kq);
            As[kq + 0][m] = v.x; As[kq + 1][m] = v.y;
            As[kq + 2][m] = v.z; As[kq + 3][m] = v.w;
        }
        {
            int k  = tid >> 4;
            int n4 = (tid & 15) << 2;
            *(float4*)&Ws[k][n4] = *(const float4*)(W + (size_t)(k0 + k) * N + col0 + n4);
        }
        __syncthreads();
        #pragma unroll
        for (int k = 0; k < 16; k++) {
            float4 a4 = *(const float4*)&As[k][ty << 2];
            float4 w4 = *(const float4*)&Ws[k][tx << 2];
            float a[4] = {a4.x, a4.y, a4.z, a4.w};
            float w[4] = {w4.x, w4.y, w4.z, w4.w};
            #pragma unroll
            for (int i = 0; i < 4; i++)
                #pragma unroll
                for (int j = 0; j < 4; j++)
                    acc[i][j] += a[i] * w[j];
        }
        __syncthreads();
    }

    #pragma unroll
    for (int i = 0; i < 4; i++) {
        int r = row0 + (ty << 2) + i;
        int c = col0 + (tx << 2);
        uint2 o = {packh2(acc[i][0] + bias[c],     acc[i][1] + bias[c + 1]),
                   packh2(acc[i][2] + bias[c + 2], acc[i][3] + bias[c + 3])};
        *(uint2*)(C + (size_t)r * N + c) = o;
    }
}

// ---------------------------------------------------------------------------
// fp16 FlashAttention (MQA), cp.async double-buffered K/V, half in/out.
// grid (S/128, B*H), 256 threads (8 warps). Softmax via exp2 with folded
// 0.125*log2(e) scale (0.125 is a power of two -> numerics unchanged).
// ---------------------------------------------------------------------------
#define SC 0.18033688011112042f   // 0.125 * log2(e)

__global__ __launch_bounds__(256, 2) void mqa_attn_h(
    const __half* __restrict__ gQ, const __half* __restrict__ gK,
    const __half* __restrict__ gV, __half* __restrict__ gatt)
{
    __shared__ __half Qs[128 * 72];
    __shared__ __half Ks[2][64 * 72];
    __shared__ __half Vs[2][64 * 72];

    const int tid  = threadIdx.x;
    const int warp = tid >> 5;
    const int lane = tid & 31;
    const int G = lane >> 2, T = lane & 3;
    const int q0 = blockIdx.x * 128;
    const int b  = blockIdx.y >> 4;
    const int h  = blockIdx.y & 15;
    const int qb = warp * 16;

    const __half* kbase = gK + (size_t)b * S_LEN * HDIM;
    const __half* vbase = gV + (size_t)b * S_LEN * HDIM;

    // K/V tile chunk mapping: 64 rows x 8 chunks (16B = 8 halves)
    const int kr = tid >> 2;            // p=0 row (0..63)
    const int kc = (tid & 3) * 8;       // chunk offsets 0,8,16,24 (+32 for p=1)

    auto load_kv = [&](int st, int kt) {
        cp16(&Ks[st][kr * 72 + kc],      kbase + (size_t)(kt + kr) * HDIM + kc);
        cp16(&Ks[st][kr * 72 + kc + 32], kbase + (size_t)(kt + kr) * HDIM + kc + 32);
        cp16(&Vs[st][kr * 72 + kc],      vbase + (size_t)(kt + kr) * HDIM + kc);
        cp16(&Vs[st][kr * 72 + kc + 32], vbase + (size_t)(kt + kr) * HDIM + kc + 32);
    };

    // Prologue: Q tile (group 0), then K/V tile 0 (group 1)
    {
        const __half* qsrc = gQ + ((size_t)(b * S_LEN + q0)) * D_MODEL + h * HDIM;
        #pragma unroll
        for (int p = 0; p < 4; p++) {
            int idx = p * 256 + tid;
            int r = idx >> 3, c8 = (idx & 7) * 8;
            cp16(&Qs[r * 72 + c8], qsrc + (size_t)r * D_MODEL + c8);
        }
    }
    cp_commit();
    load_kv(0, 0);
    cp_commit();

    cp_wait<1>();            // Q ready
    __syncthreads();

    uint32_t qf[4][4];
    #pragma unroll
    for (int kq = 0; kq < 4; kq++)
        ldsm4(qf[kq][0], qf[kq][1], qf[kq][2], qf[kq][3],
              &Qs[(qb + (lane & 15)) * 72 + kq * 16 + (lane >> 4) * 8]);

    float o_acc[8][4] = {};
    float m0 = -INFINITY, m1 = -INFINITY, l0 = 0.f, l1 = 0.f;

    const int NT = S_LEN / 64;
    for (int i = 0; i < NT; i++) {
        int st = i & 1;
        if (i + 1 < NT) load_kv(st ^ 1, (i + 1) * 64);
        cp_commit();
        cp_wait<1>();
        __syncthreads();

        // S = Q * K^T : 16 q-rows x 64 keys per warp (raw scores)
        float s[8][4];
        #pragma unroll
        for (int nt = 0; nt < 8; nt++) { s[nt][0]=0.f; s[nt][1]=0.f; s[nt][2]=0.f; s[nt][3]=0.f; }
        #pragma unroll
        for (int nt = 0; nt < 8; nt++) {
            uint32_t b0, b1, b2, b3, b4, b5, b6, b7;
            const __half* kp = &Ks[st][(nt * 8 + (lane & 7)) * 72 + ((lane >> 3) * 8)];
            ldsm4(b0, b1, b2, b3, kp);
            ldsm4(b4, b5, b6, b7, kp + 32);
            mma16816(s[nt], qf[0][0], qf[0][1], qf[0][2], qf[0][3], b0, b1);
            mma16816(s[nt], qf[1][0], qf[1][1], qf[1][2], qf[1][3], b2, b3);
            mma16816(s[nt], qf[2][0], qf[2][1], qf[2][2], qf[2][3], b4, b5);
            mma16816(s[nt], qf[3][0], qf[3][1], qf[3][2], qf[3][3], b6, b7);
        }

        // Online softmax on raw scores, exp2 with folded scale
        float mx0 = -INFINITY, mx1 = -INFINITY;
        #pragma unroll
        for (int nt = 0; nt < 8; nt++) {
            mx0 = fmaxf(mx0, fmaxf(s[nt][0], s[nt][1]));
            mx1 = fmaxf(mx1, fmaxf(s[nt][2], s[nt][3]));
        }
        mx0 = fmaxf(mx0, __shfl_xor_sync(0xffffffffu, mx0, 1));
        mx0 = fmaxf(mx0, __shfl_xor_sync(0xffffffffu, mx0, 2));
        mx1 = fmaxf(mx1, __shfl_xor_sync(0xffffffffu, mx1, 1));
        mx1 = fmaxf(mx1, __shfl_xor_sync(0xffffffffu, mx1, 2));

        float mn0 = fmaxf(m0, mx0), mn1 = fmaxf(m1, mx1);
        float r0 = 0.f, r1 = 0.f;
        #pragma unroll
        for (int nt = 0; nt < 8; nt++) {
            s[nt][0] = ex2((s[nt][0] - mn0) * SC);
            s[nt][1] = ex2((s[nt][1] - mn0) * SC);
            s[nt][2] = ex2((s[nt][2] - mn1) * SC);
            s[nt][3] = ex2((s[nt][3] - mn1) * SC);
            r0 += s[nt][0] + s[nt][1];
            r1 += s[nt][2] + s[nt][3];
        }
        r0 += __shfl_xor_sync(0xffffffffu, r0, 1);
        r0 += __shfl_xor_sync(0xffffffffu, r0, 2);
        r1 += __shfl_xor_sync(0xffffffffu, r1, 1);
        r1 += __shfl_xor_sync(0xffffffffu, r1, 2);

        if (mn0 > m0 + 0.f || mn1 > m1) {   // max moved -> rescale
            float f0 = ex2((m0 - mn0) * SC);
            float f1 = ex2((m1 - mn1) * SC);
            l0 = l0 * f0; l1 = l1 * f1;
            #pragma unroll
            for (int ht = 0; ht < 8; ht++) {
                o_acc[ht][0] *= f0; o_acc[ht][1] *= f0;
                o_acc[ht][2] *= f1; o_acc[ht][3] *= f1;
            }
        }
        l0 += r0; l1 += r1;
        m0 = mn0; m1 = mn1;

        // O += P * V : P packs straight into A fragments
        #pragma unroll
        for (int ks = 0; ks < 4; ks++) {
            uint32_t a0 = packh2(s[2*ks][0],   s[2*ks][1]);
            uint32_t a1 = packh2(s[2*ks][2],   s[2*ks][3]);
            uint32_t a2 = packh2(s[2*ks+1][0], s[2*ks+1][1]);
            uint32_t a3 = packh2(s[2*ks+1][2], s[2*ks+1][3]);
            #pragma unroll
            for (int hp = 0; hp < 4; hp++) {
                uint32_t b0, b1, b2, b3;
                ldsm4t(b0, b1, b2, b3,
                       &Vs[st][(ks * 16 + (lane & 15)) * 72 + hp * 16 + (lane >> 4) * 8]);
                mma16816(o_acc[hp * 2],     a0, a1, a2, a3, b0, b1);
                mma16816(o_acc[hp * 2 + 1], a0, a1, a2, a3, b2, b3);
            }
        }
        __syncthreads();   // all warps done with stage st before it is refilled
    }

    // Epilogue: normalize, write half
    float i0 = 1.f / l0, i1 = 1.f / l1;
    __half* od  = gatt + ((size_t)(b * S_LEN + q0 + qb + G)) * D_MODEL + h * HDIM;
    __half* od8 = od + (size_t)8 * D_MODEL;
    #pragma unroll
    for (int ht = 0; ht < 8; ht++) {
        int c = ht * 8 + 2 * T;
        *(uint32_t*)(od + c)  = packh2(o_acc[ht][0] * i0, o_acc[ht][1] * i0);
        *(uint32_t*)(od8 + c) = packh2(o_acc[ht][2] * i1, o_acc[ht][3] * i1);
    }
}

// ---------------------------------------------------------------------------
extern "C" void kernel_launch(void* const* d_in, const int* in_sizes, int n_in,
                              void* d_out, int out_size)
{
    const float* x  = (const float*)d_in[0];
    const float* Wq = (const float*)d_in[1];
    const float* bq = (const float*)d_in[2];
    const float* Wk = (const float*)d_in[3];
    const float* bk = (const float*)d_in[4];
    const float* Wv = (const float*)d_in[5];
    const float* bv = (const float*)d_in[6];
    const float* Wo = (const float*)d_in[7];
    const float* bo = (const float*)d_in[8];
    float* out = (float*)d_out;

    __half *xh, *Wqh, *Woh, *Qh, *Kh, *Vh, *ah;
    cudaGetSymbolAddress((void**)&xh,  g_xh);
    cudaGetSymbolAddress((void**)&Wqh, g_Wqh);
    cudaGetSymbolAddress((void**)&Woh, g_Woh);
    cudaGetSymbolAddress((void**)&Qh,  g_Qh);
    cudaGetSymbolAddress((void**)&Kh,  g_Kh);
    cudaGetSymbolAddress((void**)&Vh,  g_Vh);
    cudaGetSymbolAddress((void**)&ah,  g_ah);

    const int NX = M_TOT * D_MODEL;      // 4.19M
    const int NW = D_MODEL * D_MODEL;    // 1.05M

    // Converts
    f2h<<<NX / (8 * 256), 256>>>(x,  xh,  NX);
    f2h<<<NW / (8 * 256), 256>>>(Wq, Wqh, NW);
    f2h<<<NW / (8 * 256), 256>>>(Wo, Woh, NW);

    // Q projection (half in/out, tensor, async pipeline)
    gemm_h<true><<<dim3(D_MODEL / 64, M_TOT / 128), 256>>>(xh, Wqh, bq, Qh, M_TOT, D_MODEL, D_MODEL);

    // K/V projections: scalar fp32 math, half output (accuracy anchor)
    sgemm_bias_h<<<dim3(1, M_TOT / 64), 256>>>(x, Wk, bk, Kh, M_TOT, HDIM, D_MODEL);
    sgemm_bias_h<<<dim3(1, M_TOT / 64), 256>>>(x, Wv, bv, Vh, M_TOT, HDIM, D_MODEL);

    // Attention
    mqa_attn_h<<<dim3(S_LEN / 128, BATCH * NHEADS), 256>>>(Qh, Kh, Vh, ah);

    // Output projection (half in, float out)
    gemm_h<false><<<dim3(D_MODEL / 64, M_TOT / 128), 256>>>(ah, Woh, bo, out, M_TOT, D_MODEL, D_MODEL);
}

// round 6
// speedup vs baseline: 8.3430x; 1.3543x over previous
#include <cuda_runtime.h>
#include <cuda_fp16.h>
#include <math.h>
#include <stdint.h>

#define D_MODEL 1024
#define S_LEN   2048
#define BATCH   2
#define NHEADS  16
#define HDIM    64
#define M_TOT   (BATCH * S_LEN)   // 4096

// Scratch (no cudaMalloc allowed)
__device__ __half g_xh [(size_t)M_TOT * D_MODEL];
__device__ __half g_xl [(size_t)M_TOT * D_MODEL];
__device__ __half g_Wqh[(size_t)D_MODEL * D_MODEL];
__device__ __half g_Woh[(size_t)D_MODEL * D_MODEL];
__device__ __half g_Wkh[(size_t)D_MODEL * HDIM];
__device__ __half g_Wkl[(size_t)D_MODEL * HDIM];
__device__ __half g_Wvh[(size_t)D_MODEL * HDIM];
__device__ __half g_Wvl[(size_t)D_MODEL * HDIM];
__device__ __half g_Qh [(size_t)M_TOT * D_MODEL];
__device__ __half g_Kh [(size_t)M_TOT * HDIM];
__device__ __half g_Vh [(size_t)M_TOT * HDIM];
__device__ __half g_ah [(size_t)M_TOT * D_MODEL];

// ---------------------------------------------------------------------------
// helpers
// ---------------------------------------------------------------------------
__device__ __forceinline__ uint32_t s2u(const void* p) {
    return (uint32_t)__cvta_generic_to_shared(p);
}
__device__ __forceinline__ void cp16(void* s, const void* g) {
    asm volatile("cp.async.cg.shared.global [%0],[%1],16;\n" :: "r"(s2u(s)), "l"(g));
}
__device__ __forceinline__ void cp_commit() {
    asm volatile("cp.async.commit_group;\n");
}
template<int N> __device__ __forceinline__ void cp_wait() {
    asm volatile("cp.async.wait_group %0;\n" :: "n"(N));
}
__device__ __forceinline__ void ldsm4(uint32_t& r0, uint32_t& r1, uint32_t& r2, uint32_t& r3,
                                      const __half* p) {
    asm volatile("ldmatrix.sync.aligned.m8n8.x4.shared.b16 {%0,%1,%2,%3},[%4];"
                 : "=r"(r0), "=r"(r1), "=r"(r2), "=r"(r3) : "r"(s2u(p)));
}
__device__ __forceinline__ void ldsm4t(uint32_t& r0, uint32_t& r1, uint32_t& r2, uint32_t& r3,
                                       const __half* p) {
    asm volatile("ldmatrix.sync.aligned.m8n8.x4.trans.shared.b16 {%0,%1,%2,%3},[%4];"
                 : "=r"(r0), "=r"(r1), "=r"(r2), "=r"(r3) : "r"(s2u(p)));
}
__device__ __forceinline__ void mma16816(float c[4],
    uint32_t a0, uint32_t a1, uint32_t a2, uint32_t a3, uint32_t b0, uint32_t b1) {
    asm volatile(
        "mma.sync.aligned.m16n8k16.row.col.f32.f16.f16.f32 "
        "{%0,%1,%2,%3},{%4,%5,%6,%7},{%8,%9},{%0,%1,%2,%3};"
        : "+f"(c[0]), "+f"(c[1]), "+f"(c[2]), "+f"(c[3])
        : "r"(a0), "r"(a1), "r"(a2), "r"(a3), "r"(b0), "r"(b1));
}
__device__ __forceinline__ uint32_t packh2(float lo, float hi) {
    __half2 h = __floats2half2_rn(lo, hi);
    return *(uint32_t*)&h;
}
__device__ __forceinline__ float ex2(float x) {
    float y; asm("ex2.approx.f32 %0,%1;" : "=f"(y) : "f"(x)); return y;
}

// ---------------------------------------------------------------------------
// fp32 -> fp16 converts
// ---------------------------------------------------------------------------
__global__ __launch_bounds__(256) void f2h(const float* __restrict__ src,
                                           __half* __restrict__ dst, int n)
{
    int i = (blockIdx.x * 256 + threadIdx.x) * 8;
    if (i < n) {
        float4 a = *(const float4*)(src + i);
        float4 b = *(const float4*)(src + i + 4);
        uint4 o = {packh2(a.x, a.y), packh2(a.z, a.w),
                   packh2(b.x, b.y), packh2(b.z, b.w)};
        *(uint4*)(dst + i) = o;
    }
}

// hi/lo split: hi = h(v), lo = h(v - float(hi))
__global__ __launch_bounds__(256) void f2h2(const float* __restrict__ src,
                                            __half* __restrict__ dh,
                                            __half* __restrict__ dl, int n)
{
    int i = (blockIdx.x * 256 + threadIdx.x) * 8;
    if (i < n) {
        float v[8];
        *(float4*)(v)     = *(const float4*)(src + i);
        *(float4*)(v + 4) = *(const float4*)(src + i + 4);
        __half h[8], l[8];
        #pragma unroll
        for (int j = 0; j < 8; j++) {
            h[j] = __float2half_rn(v[j]);
            l[j] = __float2half_rn(v[j] - __half2float(h[j]));
        }
        *(uint4*)(dh + i) = *(uint4*)h;
        *(uint4*)(dl + i) = *(uint4*)l;
    }
}

// ---------------------------------------------------------------------------
// fp16 tensor GEMM + bias: C = A[M,K] @ W[K,N] + bias  (f32 accum)
// BM=128, BN=128, BK=32; 256 thr = 8 warps (4m x 2n, warp tile 32x64)
// 3-stage cp.async ring, 1 __syncthreads per K-tile.
// ---------------------------------------------------------------------------
template<bool OUT_HALF>
__global__ __launch_bounds__(256) void gemm_h(
    const __half* __restrict__ A, const __half* __restrict__ W,
    const float* __restrict__ bias, void* __restrict__ Cv,
    int M, int N, int K)
{
    __shared__ __half As[3][128 * 40];
    __shared__ __half Ws[3][32 * 136];

    const int tid  = threadIdx.x;
    const int warp = tid >> 5;
    const int lane = tid & 31;
    const int G = lane >> 2, T = lane & 3;
    const int wm = (warp & 3) * 32;
    const int wn = (warp >> 2) * 64;
    const int row0 = blockIdx.y * 128;
    const int col0 = blockIdx.x * 128;

    const int ar = tid >> 1;                 // 0..127
    const int ac = (tid & 1) * 16;           // 0 or 16
    const int wr = tid >> 3;                 // 0..31
    const int wc = (tid & 7) * 16;           // 0..112

    auto load_stage = [&](int st, int k0) {
        const __half* ap = A + (size_t)(row0 + ar) * K + k0 + ac;
        cp16(&As[st][ar * 40 + ac],     ap);
        cp16(&As[st][ar * 40 + ac + 8], ap + 8);
        const __half* wp = W + (size_t)(k0 + wr) * N + col0 + wc;
        cp16(&Ws[st][wr * 136 + wc],     wp);
        cp16(&Ws[st][wr * 136 + wc + 8], wp + 8);
        cp_commit();
    };

    float acc[2][8][4] = {};
    const int NK = K >> 5;

    load_stage(0, 0);
    load_stage(1, 32);

    for (int i = 0; i < NK; i++) {
        cp_wait<1>();
        __syncthreads();
        if (i + 2 < NK) load_stage((i + 2) % 3, (i + 2) << 5);
        const int st = i % 3;

        #pragma unroll
        for (int kc = 0; kc < 2; kc++) {
            uint32_t af[2][4];
            #pragma unroll
            for (int mt = 0; mt < 2; mt++)
                ldsm4(af[mt][0], af[mt][1], af[mt][2], af[mt][3],
                      &As[st][(wm + mt * 16 + (lane & 15)) * 40 + kc * 16 + (lane >> 4) * 8]);
            #pragma unroll
            for (int np = 0; np < 4; np++) {
                uint32_t b0, b1, b2, b3;
                ldsm4t(b0, b1, b2, b3,
                       &Ws[st][(kc * 16 + (lane & 15)) * 136 + wn + np * 16 + (lane >> 4) * 8]);
                #pragma unroll
                for (int mt = 0; mt < 2; mt++) {
                    mma16816(acc[mt][np * 2],     af[mt][0], af[mt][1], af[mt][2], af[mt][3], b0, b1);
                    mma16816(acc[mt][np * 2 + 1], af[mt][0], af[mt][1], af[mt][2], af[mt][3], b2, b3);
                }
            }
        }
    }

    #pragma unroll
    for (int mt = 0; mt < 2; mt++) {
        int r = row0 + wm + mt * 16 + G;
        #pragma unroll
        for (int nt = 0; nt < 8; nt++) {
            int c = col0 + wn + nt * 8 + 2 * T;
            float2 bv = *(const float2*)(bias + c);
            float v00 = acc[mt][nt][0] + bv.x, v01 = acc[mt][nt][1] + bv.y;
            float v10 = acc[mt][nt][2] + bv.x, v11 = acc[mt][nt][3] + bv.y;
            if (OUT_HALF) {
                __half* C = (__half*)Cv;
                *(uint32_t*)(C + (size_t)r * N + c)       = packh2(v00, v01);
                *(uint32_t*)(C + (size_t)(r + 8) * N + c) = packh2(v10, v11);
            } else {
                float* C = (float*)Cv;
                float2 a0 = {v00, v01}, a1 = {v10, v11};
                *(float2*)(C + (size_t)r * N + c)       = a0;
                *(float2*)(C + (size_t)(r + 8) * N + c) = a1;
            }
        }
    }
}

// ---------------------------------------------------------------------------
// K/V projection via split-fp16 (fp32-quality): C = x @ W + b, N = 64.
// x = xh + xl, W = Wh + Wl; acc += xh*Wh + xh*Wl + xl*Wh.
// BM=64, BN=64, BK=32; grid (2, M/64); blockIdx.x: 0 -> K, 1 -> V.
// ---------------------------------------------------------------------------
__global__ __launch_bounds__(256) void kv_proj(
    const __half* __restrict__ Ah, const __half* __restrict__ Al,
    const __half* __restrict__ Wkh, const __half* __restrict__ Wkl,
    const float* __restrict__ bk, __half* __restrict__ Kh,
    const __half* __restrict__ Wvh, const __half* __restrict__ Wvl,
    const float* __restrict__ bv, __half* __restrict__ Vh)
{
    __shared__ __half Ahs[2][64 * 40];
    __shared__ __half Als[2][64 * 40];
    __shared__ __half Whs[2][32 * 72];
    __shared__ __half Wls[2][32 * 72];

    const __half* Wh; const __half* Wl; const float* bias; __half* C;
    if (blockIdx.x == 0) { Wh = Wkh; Wl = Wkl; bias = bk; C = Kh; }
    else                 { Wh = Wvh; Wl = Wvl; bias = bv; C = Vh; }

    const int tid  = threadIdx.x;
    const int warp = tid >> 5;
    const int lane = tid & 31;
    const int G = lane >> 2, T = lane & 3;
    const int wm = (warp & 3) * 16;
    const int wn = (warp >> 2) * 32;
    const int row0 = blockIdx.y * 64;

    const int ar = tid >> 2;               // 0..63
    const int ac = (tid & 3) * 8;          // 0..24
    const int wr = tid >> 3;               // 0..31
    const int wc = (tid & 7) * 8;          // 0..56

    auto load_stage = [&](int st, int k0) {
        cp16(&Ahs[st][ar * 40 + ac], Ah + (size_t)(row0 + ar) * D_MODEL + k0 + ac);
        cp16(&Als[st][ar * 40 + ac], Al + (size_t)(row0 + ar) * D_MODEL + k0 + ac);
        cp16(&Whs[st][wr * 72 + wc], Wh + (size_t)(k0 + wr) * HDIM + wc);
        cp16(&Wls[st][wr * 72 + wc], Wl + (size_t)(k0 + wr) * HDIM + wc);
        cp_commit();
    };

    float acc[4][4] = {};
    const int NK = D_MODEL / 32;

    load_stage(0, 0);
    for (int i = 0; i < NK; i++) {
        int st = i & 1;
        if (i + 1 < NK) load_stage(st ^ 1, (i + 1) * 32);
        cp_wait<1>();
        __syncthreads();

        #pragma unroll
        for (int kc = 0; kc < 2; kc++) {
            uint32_t ah0, ah1, ah2, ah3, al0, al1, al2, al3;
            ldsm4(ah0, ah1, ah2, ah3,
                  &Ahs[st][(wm + (lane & 15)) * 40 + kc * 16 + (lane >> 4) * 8]);
            ldsm4(al0, al1, al2, al3,
                  &Als[st][(wm + (lane & 15)) * 40 + kc * 16 + (lane >> 4) * 8]);
            #pragma unroll
            for (int np = 0; np < 2; np++) {
                uint32_t bh0, bh1, bh2, bh3, bl0, bl1, bl2, bl3;
                ldsm4t(bh0, bh1, bh2, bh3,
                       &Whs[st][(kc * 16 + (lane & 15)) * 72 + wn + np * 16 + (lane >> 4) * 8]);
                ldsm4t(bl0, bl1, bl2, bl3,
                       &Wls[st][(kc * 16 + (lane & 15)) * 72 + wn + np * 16 + (lane >> 4) * 8]);
                mma16816(acc[np * 2],     ah0, ah1, ah2, ah3, bh0, bh1);
                mma16816(acc[np * 2 + 1], ah0, ah1, ah2, ah3, bh2, bh3);
                mma16816(acc[np * 2],     ah0, ah1, ah2, ah3, bl0, bl1);
                mma16816(acc[np * 2 + 1], ah0, ah1, ah2, ah3, bl2, bl3);
                mma16816(acc[np * 2],     al0, al1, al2, al3, bh0, bh1);
                mma16816(acc[np * 2 + 1], al0, al1, al2, al3, bh2, bh3);
            }
        }
        __syncthreads();
    }

    #pragma unroll
    for (int nt = 0; nt < 4; nt++) {
        int r = row0 + wm + G;
        int c = wn + nt * 8 + 2 * T;
        float2 bv2 = *(const float2*)(bias + c);
        *(uint32_t*)(C + (size_t)r * HDIM + c) =
            packh2(acc[nt][0] + bv2.x, acc[nt][1] + bv2.y);
        *(uint32_t*)(C + (size_t)(r + 8) * HDIM + c) =
            packh2(acc[nt][2] + bv2.x, acc[nt][3] + bv2.y);
    }
}

// ---------------------------------------------------------------------------
// fp16 FlashAttention (MQA), 3-stage cp.async ring, Q region aliased as
// stage 0 after fragments are hoisted. One __syncthreads per K/V tile.
// grid (S/128, B*H), 256 threads (8 warps, 16 q-rows each).
// ---------------------------------------------------------------------------
#define SC 0.18033688011112042f   // 0.125 * log2(e)
#define STG 9216                  // halves per stage (= 64*72*2 = Q tile 128*72)

__global__ __launch_bounds__(256, 2) void mqa_attn_h(
    const __half* __restrict__ gQ, const __half* __restrict__ gK,
    const __half* __restrict__ gV, __half* __restrict__ gatt)
{
    __shared__ __half SM[3 * STG];   // stage s: K at s*STG, V at s*STG+4608

    const int tid  = threadIdx.x;
    const int warp = tid >> 5;
    const int lane = tid & 31;
    const int G = lane >> 2, T = lane & 3;
    const int q0 = blockIdx.x * 128;
    const int b  = blockIdx.y >> 4;
    const int h  = blockIdx.y & 15;
    const int qb = warp * 16;

    const __half* kbase = gK + (size_t)b * S_LEN * HDIM;
    const __half* vbase = gV + (size_t)b * S_LEN * HDIM;

    const int kr = tid >> 2;            // 0..63
    const int kc = (tid & 3) * 8;       // 0,8,16,24

    // tile t lives in stage (t+1)%3
    auto load_kv = [&](int st, int kt) {
        __half* Kd = SM + st * STG;
        __half* Vd = Kd + 4608;
        const __half* kp = kbase + (size_t)(kt + kr) * HDIM + kc;
        const __half* vp = vbase + (size_t)(kt + kr) * HDIM + kc;
        cp16(&Kd[kr * 72 + kc],      kp);
        cp16(&Kd[kr * 72 + kc + 32], kp + 32);
        cp16(&Vd[kr * 72 + kc],      vp);
        cp16(&Vd[kr * 72 + kc + 32], vp + 32);
        cp_commit();
    };

    // Prologue: Q -> stage 0 region; K/V tiles 0,1 -> stages 1,2
    {
        const __half* qsrc = gQ + ((size_t)(b * S_LEN + q0)) * D_MODEL + h * HDIM;
        #pragma unroll
        for (int p = 0; p < 4; p++) {
            int idx = p * 256 + tid;
            int r = idx >> 3, c8 = (idx & 7) * 8;
            cp16(&SM[r * 72 + c8], qsrc + (size_t)r * D_MODEL + c8);
        }
        cp_commit();
    }
    load_kv(1, 0);
    load_kv(2, 64);

    cp_wait<2>();            // Q copies complete (this thread's groups)
    __syncthreads();         // make ALL threads' Q copies visible before ldsm
    uint32_t qf[4][4];
    #pragma unroll
    for (int kq = 0; kq < 4; kq++)
        ldsm4(qf[kq][0], qf[kq][1], qf[kq][2], qf[kq][3],
              &SM[(qb + (lane & 15)) * 72 + kq * 16 + (lane >> 4) * 8]);

    float o_acc[8][4] = {};
    float m0 = -INFINITY, m1 = -INFINITY, l0 = 0.f, l1 = 0.f;

    const int NT = S_LEN / 64;
    for (int i = 0; i < NT; i++) {
        cp_wait<1>();        // tile i ready (this thread)
        __syncthreads();     // visibility across threads; prev compute done before refill
        if (i + 2 < NT) load_kv(i % 3, (i + 2) * 64);
        const int st = (i + 1) % 3;
        const __half* Ks = SM + st * STG;
        const __half* Vs = Ks + 4608;

        // S = Q * K^T : 16 q-rows x 64 keys per warp
        float s[8][4];
        #pragma unroll
        for (int nt = 0; nt < 8; nt++) { s[nt][0]=0.f; s[nt][1]=0.f; s[nt][2]=0.f; s[nt][3]=0.f; }
        #pragma unroll
        for (int nt = 0; nt < 8; nt++) {
            uint32_t b0, b1, b2, b3, b4, b5, b6, b7;
            const __half* kp = &Ks[(nt * 8 + (lane & 7)) * 72 + ((lane >> 3) * 8)];
            ldsm4(b0, b1, b2, b3, kp);
            ldsm4(b4, b5, b6, b7, kp + 32);
            mma16816(s[nt], qf[0][0], qf[0][1], qf[0][2], qf[0][3], b0, b1);
            mma16816(s[nt], qf[1][0], qf[1][1], qf[1][2], qf[1][3], b2, b3);
            mma16816(s[nt], qf[2][0], qf[2][1], qf[2][2], qf[2][3], b4, b5);
            mma16816(s[nt], qf[3][0], qf[3][1], qf[3][2], qf[3][3], b6, b7);
        }

        // Online softmax, exp2 with folded 0.125*log2e scale
        float mx0 = -INFINITY, mx1 = -INFINITY;
        #pragma unroll
        for (int nt = 0; nt < 8; nt++) {
            mx0 = fmaxf(mx0, fmaxf(s[nt][0], s[nt][1]));
            mx1 = fmaxf(mx1, fmaxf(s[nt][2], s[nt][3]));
        }
        mx0 = fmaxf(mx0, __shfl_xor_sync(0xffffffffu, mx0, 1));
        mx0 = fmaxf(mx0, __shfl_xor_sync(0xffffffffu, mx0, 2));
        mx1 = fmaxf(mx1, __shfl_xor_sync(0xffffffffu, mx1, 1));
        mx1 = fmaxf(mx1, __shfl_xor_sync(0xffffffffu, mx1, 2));

        float mn0 = fmaxf(m0, mx0), mn1 = fmaxf(m1, mx1);
        float r0 = 0.f, r1 = 0.f;
        #pragma unroll
        for (int nt = 0; nt < 8; nt++) {
            s[nt][0] = ex2((s[nt][0] - mn0) * SC);
            s[nt][1] = ex2((s[nt][1] - mn0) * SC);
            s[nt][2] = ex2((s[nt][2] - mn1) * SC);
            s[nt][3] = ex2((s[nt][3] - mn1) * SC);
            r0 += s[nt][0] + s[nt][1];
            r1 += s[nt][2] + s[nt][3];
        }
        r0 += __shfl_xor_sync(0xffffffffu, r0, 1);
        r0 += __shfl_xor_sync(0xffffffffu, r0, 2);
        r1 += __shfl_xor_sync(0xffffffffu, r1, 1);
        r1 += __shfl_xor_sync(0xffffffffu, r1, 2);

        if (mn0 > m0 || mn1 > m1) {
            float f0 = ex2((m0 - mn0) * SC);
            float f1 = ex2((m1 - mn1) * SC);
            l0 *= f0; l1 *= f1;
            #pragma unroll
            for (int ht = 0; ht < 8; ht++) {
                o_acc[ht][0] *= f0; o_acc[ht][1] *= f0;
                o_acc[ht][2] *= f1; o_acc[ht][3] *= f1;
            }
        }
        l0 += r0; l1 += r1;
        m0 = mn0; m1 = mn1;

        // O += P * V : P packs straight into A fragments
        #pragma unroll
        for (int ks = 0; ks < 4; ks++) {
            uint32_t a0 = packh2(s[2*ks][0],   s[2*ks][1]);
            uint32_t a1 = packh2(s[2*ks][2],   s[2*ks][3]);
            uint32_t a2 = packh2(s[2*ks+1][0], s[2*ks+1][1]);
            uint32_t a3 = packh2(s[2*ks+1][2], s[2*ks+1][3]);
            #pragma unroll
            for (int hp = 0; hp < 4; hp++) {
                uint32_t b0, b1, b2, b3;
                ldsm4t(b0, b1, b2, b3,
                       &Vs[(ks * 16 + (lane & 15)) * 72 + hp * 16 + (lane >> 4) * 8]);
                mma16816(o_acc[hp * 2],     a0, a1, a2, a3, b0, b1);
                mma16816(o_acc[hp * 2 + 1], a0, a1, a2, a3, b2, b3);
            }
        }
    }

    // Epilogue: normalize, write half
    float i0 = 1.f / l0, i1 = 1.f / l1;
    __half* od  = gatt + ((size_t)(b * S_LEN + q0 + qb + G)) * D_MODEL + h * HDIM;
    __half* od8 = od + (size_t)8 * D_MODEL;
    #pragma unroll
    for (int ht = 0; ht < 8; ht++) {
        int c = ht * 8 + 2 * T;
        *(uint32_t*)(od + c)  = packh2(o_acc[ht][0] * i0, o_acc[ht][1] * i0);
        *(uint32_t*)(od8 + c) = packh2(o_acc[ht][2] * i1, o_acc[ht][3] * i1);
    }
}

// ---------------------------------------------------------------------------
extern "C" void kernel_launch(void* const* d_in, const int* in_sizes, int n_in,
                              void* d_out, int out_size)
{
    const float* x  = (const float*)d_in[0];
    const float* Wq = (const float*)d_in[1];
    const float* bq = (const float*)d_in[2];
    const float* Wk = (const float*)d_in[3];
    const float* bk = (const float*)d_in[4];
    const float* Wv = (const float*)d_in[5];
    const float* bv = (const float*)d_in[6];
    const float* Wo = (const float*)d_in[7];
    const float* bo = (const float*)d_in[8];
    float* out = (float*)d_out;

    __half *xh, *xl, *Wqh, *Woh, *Wkh, *Wkl, *Wvh, *Wvl, *Qh, *Kh, *Vh, *ah;
    cudaGetSymbolAddress((void**)&xh,  g_xh);
    cudaGetSymbolAddress((void**)&xl,  g_xl);
    cudaGetSymbolAddress((void**)&Wqh, g_Wqh);
    cudaGetSymbolAddress((void**)&Woh, g_Woh);
    cudaGetSymbolAddress((void**)&Wkh, g_Wkh);
    cudaGetSymbolAddress((void**)&Wkl, g_Wkl);
    cudaGetSymbolAddress((void**)&Wvh, g_Wvh);
    cudaGetSymbolAddress((void**)&Wvl, g_Wvl);
    cudaGetSymbolAddress((void**)&Qh,  g_Qh);
    cudaGetSymbolAddress((void**)&Kh,  g_Kh);
    cudaGetSymbolAddress((void**)&Vh,  g_Vh);
    cudaGetSymbolAddress((void**)&ah,  g_ah);

    const int NX = M_TOT * D_MODEL;      // 4.19M
    const int NW = D_MODEL * D_MODEL;    // 1.05M
    const int NS = D_MODEL * HDIM;       // 65.5K

    // Converts
    f2h2<<<NX / 2048, 256>>>(x,  xh, xl, NX);
    f2h <<<NW / 2048, 256>>>(Wq, Wqh, NW);
    f2h <<<NW / 2048, 256>>>(Wo, Woh, NW);
    f2h2<<<NS / 2048, 256>>>(Wk, Wkh, Wkl, NS);
    f2h2<<<NS / 2048, 256>>>(Wv, Wvh, Wvl, NS);

    // Q projection (fp16 tensor)
    gemm_h<true><<<dim3(D_MODEL / 128, M_TOT / 128), 256>>>(xh, Wqh, bq, Qh, M_TOT, D_MODEL, D_MODEL);

    // K/V projections (split-fp16 tensor, fp32 quality)
    kv_proj<<<dim3(2, M_TOT / 64), 256>>>(xh, xl, Wkh, Wkl, bk, Kh, Wvh, Wvl, bv, Vh);

    // Attention
    mqa_attn_h<<<dim3(S_LEN / 128, BATCH * NHEADS), 256>>>(Qh, Kh, Vh, ah);

    // Output projection (half in, float out)
    gemm_h<false><<<dim3(D_MODEL / 128, M_TOT / 128), 256>>>(ah, Woh, bo, out, M_TOT, D_MODEL, D_MODEL);
}

// round 12
// speedup vs baseline: 8.5605x; 1.0261x over previous
#include <cuda_runtime.h>
#include <cuda_fp16.h>
#include <math.h>
#include <stdint.h>

#define D_MODEL 1024
#define S_LEN   2048
#define BATCH   2
#define NHEADS  16
#define HDIM    64
#define M_TOT   (BATCH * S_LEN)   // 4096

// Scratch (no cudaMalloc allowed)
__device__ __half g_xh [(size_t)M_TOT * D_MODEL];
__device__ __half g_xl [(size_t)M_TOT * D_MODEL];
__device__ __half g_Wqh[(size_t)D_MODEL * D_MODEL];
__device__ __half g_Woh[(size_t)D_MODEL * D_MODEL];
__device__ __half g_Wkh[(size_t)D_MODEL * HDIM];
__device__ __half g_Wkl[(size_t)D_MODEL * HDIM];
__device__ __half g_Wvh[(size_t)D_MODEL * HDIM];
__device__ __half g_Wvl[(size_t)D_MODEL * HDIM];
__device__ __half g_Qh [(size_t)M_TOT * D_MODEL];
__device__ __half g_Kh [(size_t)M_TOT * HDIM];
__device__ __half g_Vh [(size_t)M_TOT * HDIM];
__device__ __half g_ah [(size_t)M_TOT * D_MODEL];

// ---------------------------------------------------------------------------
// helpers
// ---------------------------------------------------------------------------
__device__ __forceinline__ uint32_t s2u(const void* p) {
    return (uint32_t)__cvta_generic_to_shared(p);
}
__device__ __forceinline__ void cp16(void* s, const void* g) {
    asm volatile("cp.async.cg.shared.global [%0],[%1],16;\n" :: "r"(s2u(s)), "l"(g));
}
__device__ __forceinline__ void cp_commit() {
    asm volatile("cp.async.commit_group;\n");
}
template<int N> __device__ __forceinline__ void cp_wait() {
    asm volatile("cp.async.wait_group %0;\n" :: "n"(N));
}
__device__ __forceinline__ void ldsm4(uint32_t& r0, uint32_t& r1, uint32_t& r2, uint32_t& r3,
                                      const __half* p) {
    asm volatile("ldmatrix.sync.aligned.m8n8.x4.shared.b16 {%0,%1,%2,%3},[%4];"
                 : "=r"(r0), "=r"(r1), "=r"(r2), "=r"(r3) : "r"(s2u(p)));
}
__device__ __forceinline__ void ldsm4t(uint32_t& r0, uint32_t& r1, uint32_t& r2, uint32_t& r3,
                                       const __half* p) {
    asm volatile("ldmatrix.sync.aligned.m8n8.x4.trans.shared.b16 {%0,%1,%2,%3},[%4];"
                 : "=r"(r0), "=r"(r1), "=r"(r2), "=r"(r3) : "r"(s2u(p)));
}
__device__ __forceinline__ void mma16816(float c[4],
    uint32_t a0, uint32_t a1, uint32_t a2, uint32_t a3, uint32_t b0, uint32_t b1) {
    asm volatile(
        "mma.sync.aligned.m16n8k16.row.col.f32.f16.f16.f32 "
        "{%0,%1,%2,%3},{%4,%5,%6,%7},{%8,%9},{%0,%1,%2,%3};"
        : "+f"(c[0]), "+f"(c[1]), "+f"(c[2]), "+f"(c[3])
        : "r"(a0), "r"(a1), "r"(a2), "r"(a3), "r"(b0), "r"(b1));
}
__device__ __forceinline__ uint32_t packh2(float lo, float hi) {
    __half2 h = __floats2half2_rn(lo, hi);
    return *(uint32_t*)&h;
}
__device__ __forceinline__ float ex2(float x) {
    float y; asm("ex2.approx.f32 %0,%1;" : "=f"(y) : "f"(x)); return y;
}

// ---------------------------------------------------------------------------
// Fused fp32 -> fp16 convert for ALL operands in ONE launch (bit-identical
// per-element math to the separate f2h/f2h2 launches; proven by R10 first-check).
// Block ranges: [0,2048) x-split, [2048,2560) Wq, [2560,3072) Wo,
//               [3072,3104) Wk-split, [3104,3136) Wv-split.
// ---------------------------------------------------------------------------
__global__ __launch_bounds__(256) void conv_all(
    const float* __restrict__ x,  __half* __restrict__ xh,  __half* __restrict__ xl,
    const float* __restrict__ Wq, __half* __restrict__ Wqh,
    const float* __restrict__ Wo, __half* __restrict__ Woh,
    const float* __restrict__ Wk, __half* __restrict__ Wkh, __half* __restrict__ Wkl,
    const float* __restrict__ Wv, __half* __restrict__ Wvh, __half* __restrict__ Wvl)
{
    int b = blockIdx.x;
    const float* src; __half* dh; __half* dl;
    if (b < 2048)      { src = x;  dh = xh;  dl = xl;  }
    else if (b < 2560) { src = Wq; dh = Wqh; dl = 0; b -= 2048; }
    else if (b < 3072) { src = Wo; dh = Woh; dl = 0; b -= 2560; }
    else if (b < 3104) { src = Wk; dh = Wkh; dl = Wkl; b -= 3072; }
    else               { src = Wv; dh = Wvh; dl = Wvl; b -= 3104; }

    int i = (b * 256 + threadIdx.x) * 8;
    float v[8];
    *(float4*)(v)     = *(const float4*)(src + i);
    *(float4*)(v + 4) = *(const float4*)(src + i + 4);
    __half h[8];
    #pragma unroll
    for (int j = 0; j < 8; j++) h[j] = __float2half_rn(v[j]);
    *(uint4*)(dh + i) = *(uint4*)h;
    if (dl) {
        __half l[8];
        #pragma unroll
        for (int j = 0; j < 8; j++)
            l[j] = __float2half_rn(v[j] - __half2float(h[j]));
        *(uint4*)(dl + i) = *(uint4*)l;
    }
}

// ---------------------------------------------------------------------------
// fp16 tensor GEMM + bias: C = A[M,K] @ W[K,N] + bias  (f32 accum)
// BM=128, BN=128, BK=32; 256 thr = 8 warps (4m x 2n, warp tile 32x64)
// 3-stage cp.async ring. FIX: cp_commit is UNCONDITIONAL every iteration so
// cp_wait<1> always forces the current tile's group to completion (the
// conditional commit made the final-tile wait a no-op -> flaky race).
// ---------------------------------------------------------------------------
template<bool OUT_HALF>
__global__ __launch_bounds__(256) void gemm_h(
    const __half* __restrict__ A, const __half* __restrict__ W,
    const float* __restrict__ bias, void* __restrict__ Cv,
    int M, int N, int K)
{
    __shared__ __half As[3][128 * 40];
    __shared__ __half Ws[3][32 * 136];

    const int tid  = threadIdx.x;
    const int warp = tid >> 5;
    const int lane = tid & 31;
    const int G = lane >> 2, T = lane & 3;
    const int wm = (warp & 3) * 32;
    const int wn = (warp >> 2) * 64;
    const int row0 = blockIdx.y * 128;
    const int col0 = blockIdx.x * 128;

    const int ar = tid >> 1;                 // 0..127
    const int ac = (tid & 1) * 16;           // 0 or 16
    const int wr = tid >> 3;                 // 0..31
    const int wc = (tid & 7) * 16;           // 0..112

    auto load_stage = [&](int st, int k0) {  // NOTE: no commit inside
        const __half* ap = A + (size_t)(row0 + ar) * K + k0 + ac;
        cp16(&As[st][ar * 40 + ac],     ap);
        cp16(&As[st][ar * 40 + ac + 8], ap + 8);
        const __half* wp = W + (size_t)(k0 + wr) * N + col0 + wc;
        cp16(&Ws[st][wr * 136 + wc],     wp);
        cp16(&Ws[st][wr * 136 + wc + 8], wp + 8);
    };

    float acc[2][8][4] = {};
    const int NK = K >> 5;

    load_stage(0, 0);  cp_commit();
    load_stage(1, 32); cp_commit();

    for (int i = 0; i < NK; i++) {
        cp_wait<1>();
        __syncthreads();
        if (i + 2 < NK) load_stage((i + 2) % 3, (i + 2) << 5);
        cp_commit();            // unconditional: keeps group count honest
        const int st = i % 3;

        #pragma unroll
        for (int kc = 0; kc < 2; kc++) {
            uint32_t af[2][4];
            #pragma unroll
            for (int mt = 0; mt < 2; mt++)
                ldsm4(af[mt][0], af[mt][1], af[mt][2], af[mt][3],
                      &As[st][(wm + mt * 16 + (lane & 15)) * 40 + kc * 16 + (lane >> 4) * 8]);
            #pragma unroll
            for (int np = 0; np < 4; np++) {
                uint32_t b0, b1, b2, b3;
                ldsm4t(b0, b1, b2, b3,
                       &Ws[st][(kc * 16 + (lane & 15)) * 136 + wn + np * 16 + (lane >> 4) * 8]);
                #pragma unroll
                for (int mt = 0; mt < 2; mt++) {
                    mma16816(acc[mt][np * 2],     af[mt][0], af[mt][1], af[mt][2], af[mt][3], b0, b1);
                    mma16816(acc[mt][np * 2 + 1], af[mt][0], af[mt][1], af[mt][2], af[mt][3], b2, b3);
                }
            }
        }
    }

    #pragma unroll
    for (int mt = 0; mt < 2; mt++) {
        int r = row0 + wm + mt * 16 + G;
        #pragma unroll
        for (int nt = 0; nt < 8; nt++) {
            int c = col0 + wn + nt * 8 + 2 * T;
            float2 bv = *(const float2*)(bias + c);
            float v00 = acc[mt][nt][0] + bv.x, v01 = acc[mt][nt][1] + bv.y;
            float v10 = acc[mt][nt][2] + bv.x, v11 = acc[mt][nt][3] + bv.y;
            if (OUT_HALF) {
                __half* C = (__half*)Cv;
                *(uint32_t*)(C + (size_t)r * N + c)       = packh2(v00, v01);
                *(uint32_t*)(C + (size_t)(r + 8) * N + c) = packh2(v10, v11);
            } else {
                float* C = (float*)Cv;
                float2 a0 = {v00, v01}, a1 = {v10, v11};
                *(float2*)(C + (size_t)r * N + c)       = a0;
                *(float2*)(C + (size_t)(r + 8) * N + c) = a1;
            }
        }
    }
}

// ---------------------------------------------------------------------------
// K/V projection via split-fp16 (fp32-quality): C = x @ W + b, N = 64.
// BM=64, BN=64, BK=32; grid (2, M/64). Same unconditional-commit fix.
// ---------------------------------------------------------------------------
__global__ __launch_bounds__(256) void kv_proj(
    const __half* __restrict__ Ah, const __half* __restrict__ Al,
    const __half* __restrict__ Wkh, const __half* __restrict__ Wkl,
    const float* __restrict__ bk, __half* __restrict__ Kh,
    const __half* __restrict__ Wvh, const __half* __restrict__ Wvl,
    const float* __restrict__ bv, __half* __restrict__ Vh)
{
    __shared__ __half Ahs[2][64 * 40];
    __shared__ __half Als[2][64 * 40];
    __shared__ __half Whs[2][32 * 72];
    __shared__ __half Wls[2][32 * 72];

    const __half* Wh; const __half* Wl; const float* bias; __half* C;
    if (blockIdx.x == 0) { Wh = Wkh; Wl = Wkl; bias = bk; C = Kh; }
    else                 { Wh = Wvh; Wl = Wvl; bias = bv; C = Vh; }

    const int tid  = threadIdx.x;
    const int warp = tid >> 5;
    const int lane = tid & 31;
    const int G = lane >> 2, T = lane & 3;
    const int wm = (warp & 3) * 16;
    const int wn = (warp >> 2) * 32;
    const int row0 = blockIdx.y * 64;

    const int ar = tid >> 2;
    const int ac = (tid & 3) * 8;
    const int wr = tid >> 3;
    const int wc = (tid & 7) * 8;

    auto load_stage = [&](int st, int k0) {  // no commit inside
        cp16(&Ahs[st][ar * 40 + ac], Ah + (size_t)(row0 + ar) * D_MODEL + k0 + ac);
        cp16(&Als[st][ar * 40 + ac], Al + (size_t)(row0 + ar) * D_MODEL + k0 + ac);
        cp16(&Whs[st][wr * 72 + wc], Wh + (size_t)(k0 + wr) * HDIM + wc);
        cp16(&Wls[st][wr * 72 + wc], Wl + (size_t)(k0 + wr) * HDIM + wc);
    };

    float acc[4][4] = {};
    const int NK = D_MODEL / 32;

    load_stage(0, 0); cp_commit();
    for (int i = 0; i < NK; i++) {
        int st = i & 1;
        if (i + 1 < NK) load_stage(st ^ 1, (i + 1) * 32);
        cp_commit();            // unconditional
        cp_wait<1>();
        __syncthreads();

        #pragma unroll
        for (int kc = 0; kc < 2; kc++) {
            uint32_t ah0, ah1, ah2, ah3, al0, al1, al2, al3;
            ldsm4(ah0, ah1, ah2, ah3,
                  &Ahs[st][(wm + (lane & 15)) * 40 + kc * 16 + (lane >> 4) * 8]);
            ldsm4(al0, al1, al2, al3,
                  &Als[st][(wm + (lane & 15)) * 40 + kc * 16 + (lane >> 4) * 8]);
            #pragma unroll
            for (int np = 0; np < 2; np++) {
                uint32_t bh0, bh1, bh2, bh3, bl0, bl1, bl2, bl3;
                ldsm4t(bh0, bh1, bh2, bh3,
                       &Whs[st][(kc * 16 + (lane & 15)) * 72 + wn + np * 16 + (lane >> 4) * 8]);
                ldsm4t(bl0, bl1, bl2, bl3,
                       &Wls[st][(kc * 16 + (lane & 15)) * 72 + wn + np * 16 + (lane >> 4) * 8]);
                mma16816(acc[np * 2],     ah0, ah1, ah2, ah3, bh0, bh1);
                mma16816(acc[np * 2 + 1], ah0, ah1, ah2, ah3, bh2, bh3);
                mma16816(acc[np * 2],     ah0, ah1, ah2, ah3, bl0, bl1);
                mma16816(acc[np * 2 + 1], ah0, ah1, ah2, ah3, bl2, bl3);
                mma16816(acc[np * 2],     al0, al1, al2, al3, bh0, bh1);
                mma16816(acc[np * 2 + 1], al0, al1, al2, al3, bh2, bh3);
            }
        }
        __syncthreads();
    }

    #pragma unroll
    for (int nt = 0; nt < 4; nt++) {
        int r = row0 + wm + G;
        int c = wn + nt * 8 + 2 * T;
        float2 bv2 = *(const float2*)(bias + c);
        *(uint32_t*)(C + (size_t)r * HDIM + c) =
            packh2(acc[nt][0] + bv2.x, acc[nt][1] + bv2.y);
        *(uint32_t*)(C + (size_t)(r + 8) * HDIM + c) =
            packh2(acc[nt][2] + bv2.x, acc[nt][3] + bv2.y);
    }
}

// ---------------------------------------------------------------------------
// fp16 FlashAttention (MQA), 3-stage cp.async ring, Q region aliased as
// stage 0 after fragments are hoisted. FP math byte-identical to R6 (FROZEN).
// FIX: unconditional cp_commit per iteration (same race as gemm).
// grid (S/128, B*H), 256 threads (8 warps, 16 q-rows each).
// ---------------------------------------------------------------------------
#define SC 0.18033688011112042f   // 0.125 * log2(e)
#define STG 9216                  // halves per stage

__global__ __launch_bounds__(256, 2) void mqa_attn_h(
    const __half* __restrict__ gQ, const __half* __restrict__ gK,
    const __half* __restrict__ gV, __half* __restrict__ gatt)
{
    __shared__ __half SM[3 * STG];

    const int tid  = threadIdx.x;
    const int warp = tid >> 5;
    const int lane = tid & 31;
    const int G = lane >> 2, T = lane & 3;
    const int q0 = blockIdx.x * 128;
    const int b  = blockIdx.y >> 4;
    const int h  = blockIdx.y & 15;
    const int qb = warp * 16;

    const __half* kbase = gK + (size_t)b * S_LEN * HDIM;
    const __half* vbase = gV + (size_t)b * S_LEN * HDIM;

    const int kr = tid >> 2;
    const int kc = (tid & 3) * 8;

    auto load_kv = [&](int st, int kt) {   // no commit inside
        __half* Kd = SM + st * STG;
        __half* Vd = Kd + 4608;
        const __half* kp = kbase + (size_t)(kt + kr) * HDIM + kc;
        const __half* vp = vbase + (size_t)(kt + kr) * HDIM + kc;
        cp16(&Kd[kr * 72 + kc],      kp);
        cp16(&Kd[kr * 72 + kc + 32], kp + 32);
        cp16(&Vd[kr * 72 + kc],      vp);
        cp16(&Vd[kr * 72 + kc + 32], vp + 32);
    };

    {
        const __half* qsrc = gQ + ((size_t)(b * S_LEN + q0)) * D_MODEL + h * HDIM;
        #pragma unroll
        for (int p = 0; p < 4; p++) {
            int idx = p * 256 + tid;
            int r = idx >> 3, c8 = (idx & 7) * 8;
            cp16(&SM[r * 72 + c8], qsrc + (size_t)r * D_MODEL + c8);
        }
        cp_commit();
    }
    load_kv(1, 0);  cp_commit();
    load_kv(2, 64); cp_commit();

    cp_wait<2>();            // Q group complete (this thread)
    __syncthreads();         // all threads' Q copies visible
    uint32_t qf[4][4];
    #pragma unroll
    for (int kq = 0; kq < 4; kq++)
        ldsm4(qf[kq][0], qf[kq][1], qf[kq][2], qf[kq][3],
              &SM[(qb + (lane & 15)) * 72 + kq * 16 + (lane >> 4) * 8]);

    float o_acc[8][4] = {};
    float m0 = -INFINITY, m1 = -INFINITY, l0 = 0.f, l1 = 0.f;

    const int NT = S_LEN / 64;
    for (int i = 0; i < NT; i++) {
        cp_wait<1>();
        __syncthreads();     // tile i visible to all; prior reads done before refill
        if (i + 2 < NT) load_kv(i % 3, (i + 2) * 64);
        cp_commit();         // unconditional: cp_wait<1> always forces tile i
        const int st = (i + 1) % 3;
        const __half* Ks = SM + st * STG;
        const __half* Vs = Ks + 4608;

        // S = Q * K^T : 16 q-rows x 64 keys per warp
        float s[8][4];
        #pragma unroll
        for (int nt = 0; nt < 8; nt++) { s[nt][0]=0.f; s[nt][1]=0.f; s[nt][2]=0.f; s[nt][3]=0.f; }
        #pragma unroll
        for (int nt = 0; nt < 8; nt++) {
            uint32_t b0, b1, b2, b3, b4, b5, b6, b7;
            const __half* kp = &Ks[(nt * 8 + (lane & 7)) * 72 + ((lane >> 3) * 8)];
            ldsm4(b0, b1, b2, b3, kp);
            ldsm4(b4, b5, b6, b7, kp + 32);
            mma16816(s[nt], qf[0][0], qf[0][1], qf[0][2], qf[0][3], b0, b1);
            mma16816(s[nt], qf[1][0], qf[1][1], qf[1][2], qf[1][3], b2, b3);
            mma16816(s[nt], qf[2][0], qf[2][1], qf[2][2], qf[2][3], b4, b5);
            mma16816(s[nt], qf[3][0], qf[3][1], qf[3][2], qf[3][3], b6, b7);
        }

        // Online softmax, exp2 with folded 0.125*log2e scale (FROZEN)
        float mx0 = -INFINITY, mx1 = -INFINITY;
        #pragma unroll
        for (int nt = 0; nt < 8; nt++) {
            mx0 = fmaxf(mx0, fmaxf(s[nt][0], s[nt][1]));
            mx1 = fmaxf(mx1, fmaxf(s[nt][2], s[nt][3]));
        }
        mx0 = fmaxf(mx0, __shfl_xor_sync(0xffffffffu, mx0, 1));
        mx0 = fmaxf(mx0, __shfl_xor_sync(0xffffffffu, mx0, 2));
        mx1 = fmaxf(mx1, __shfl_xor_sync(0xffffffffu, mx1, 1));
        mx1 = fmaxf(mx1, __shfl_xor_sync(0xffffffffu, mx1, 2));

        float mn0 = fmaxf(m0, mx0), mn1 = fmaxf(m1, mx1);
        float r0 = 0.f, r1 = 0.f;
        #pragma unroll
        for (int nt = 0; nt < 8; nt++) {
            s[nt][0] = ex2((s[nt][0] - mn0) * SC);
            s[nt][1] = ex2((s[nt][1] - mn0) * SC);
            s[nt][2] = ex2((s[nt][2] - mn1) * SC);
            s[nt][3] = ex2((s[nt][3] - mn1) * SC);
            r0 += s[nt][0] + s[nt][1];
            r1 += s[nt][2] + s[nt][3];
        }
        r0 += __shfl_xor_sync(0xffffffffu, r0, 1);
        r0 += __shfl_xor_sync(0xffffffffu, r0, 2);
        r1 += __shfl_xor_sync(0xffffffffu, r1, 1);
        r1 += __shfl_xor_sync(0xffffffffu, r1, 2);

        if (mn0 > m0 || mn1 > m1) {
            float f0 = ex2((m0 - mn0) * SC);
            float f1 = ex2((m1 - mn1) * SC);
            l0 *= f0; l1 *= f1;
            #pragma unroll
            for (int ht = 0; ht < 8; ht++) {
                o_acc[ht][0] *= f0; o_acc[ht][1] *= f0;
                o_acc[ht][2] *= f1; o_acc[ht][3] *= f1;
            }
        }
        l0 += r0; l1 += r1;
        m0 = mn0; m1 = mn1;

        // O += P * V : P packs straight into A fragments
        #pragma unroll
        for (int ks = 0; ks < 4; ks++) {
            uint32_t a0 = packh2(s[2*ks][0],   s[2*ks][1]);
            uint32_t a1 = packh2(s[2*ks][2],   s[2*ks][3]);
            uint32_t a2 = packh2(s[2*ks+1][0], s[2*ks+1][1]);
            uint32_t a3 = packh2(s[2*ks+1][2], s[2*ks+1][3]);
            #pragma unroll
            for (int hp = 0; hp < 4; hp++) {
                uint32_t b0, b1, b2, b3;
                ldsm4t(b0, b1, b2, b3,
                       &Vs[(ks * 16 + (lane & 15)) * 72 + hp * 16 + (lane >> 4) * 8]);
                mma16816(o_acc[hp * 2],     a0, a1, a2, a3, b0, b1);
                mma16816(o_acc[hp * 2 + 1], a0, a1, a2, a3, b2, b3);
            }
        }
    }

    // Epilogue: normalize, write half
    float i0 = 1.f / l0, i1 = 1.f / l1;
    __half* od  = gatt + ((size_t)(b * S_LEN + q0 + qb + G)) * D_MODEL + h * HDIM;
    __half* od8 = od + (size_t)8 * D_MODEL;
    #pragma unroll
    for (int ht = 0; ht < 8; ht++) {
        int c = ht * 8 + 2 * T;
        *(uint32_t*)(od + c)  = packh2(o_acc[ht][0] * i0, o_acc[ht][1] * i0);
        *(uint32_t*)(od8 + c) = packh2(o_acc[ht][2] * i1, o_acc[ht][3] * i1);
    }
}

// ---------------------------------------------------------------------------
extern "C" void kernel_launch(void* const* d_in, const int* in_sizes, int n_in,
                              void* d_out, int out_size)
{
    const float* x  = (const float*)d_in[0];
    const float* Wq = (const float*)d_in[1];
    const float* bq = (const float*)d_in[2];
    const float* Wk = (const float*)d_in[3];
    const float* bk = (const float*)d_in[4];
    const float* Wv = (const float*)d_in[5];
    const float* bv = (const float*)d_in[6];
    const float* Wo = (const float*)d_in[7];
    const float* bo = (const float*)d_in[8];
    float* out = (float*)d_out;

    __half *xh, *xl, *Wqh, *Woh, *Wkh, *Wkl, *Wvh, *Wvl, *Qh, *Kh, *Vh, *ah;
    cudaGetSymbolAddress((void**)&xh,  g_xh);
    cudaGetSymbolAddress((void**)&xl,  g_xl);
    cudaGetSymbolAddress((void**)&Wqh, g_Wqh);
    cudaGetSymbolAddress((void**)&Woh, g_Woh);
    cudaGetSymbolAddress((void**)&Wkh, g_Wkh);
    cudaGetSymbolAddress((void**)&Wkl, g_Wkl);
    cudaGetSymbolAddress((void**)&Wvh, g_Wvh);
    cudaGetSymbolAddress((void**)&Wvl, g_Wvl);
    cudaGetSymbolAddress((void**)&Qh,  g_Qh);
    cudaGetSymbolAddress((void**)&Kh,  g_Kh);
    cudaGetSymbolAddress((void**)&Vh,  g_Vh);
    cudaGetSymbolAddress((void**)&ah,  g_ah);

    // One fused convert launch (bit-identical outputs)
    conv_all<<<3136, 256>>>(x, xh, xl, Wq, Wqh, Wo, Woh,
                            Wk, Wkh, Wkl, Wv, Wvh, Wvl);

    // Q projection (fp16 tensor)
    gemm_h<true><<<dim3(D_MODEL / 128, M_TOT / 128), 256>>>(xh, Wqh, bq, Qh, M_TOT, D_MODEL, D_MODEL);

    // K/V projections (split-fp16 tensor, fp32 quality)
    kv_proj<<<dim3(2, M_TOT / 64), 256>>>(xh, xl, Wkh, Wkl, bk, Kh, Wvh, Wvl, bv, Vh);

    // Attention
    mqa_attn_h<<<dim3(S_LEN / 128, BATCH * NHEADS), 256>>>(Qh, Kh, Vh, ah);

    // Output projection (half in, float out)
    gemm_h<false><<<dim3(D_MODEL / 128, M_TOT / 128), 256>>>(ah, Woh, bo, out, M_TOT, D_MODEL, D_MODEL);
}